// round 10
// baseline (speedup 1.0000x reference)
#include <cuda_runtime.h>
#include <cuda_bf16.h>
#include <math.h>

#define Nn 16
#define Cc 64
#define Tt 300
#define Vv 25
#define NHh 4
#define Bb (Nn*Vv)          // 400
#define QKVO 192            // 2*DK+DV

__device__ float g_qkv[(size_t)Bb * QKVO * Tt];
__device__ float g_attn[(size_t)Bb * 64 * Tt];

// ---- packed fp32 helpers (FFMA2 / FMUL2 are PTX-only on sm_103a) ----
__device__ __forceinline__ float2 ffma2(float2 a, float2 b, float2 c) {
    unsigned long long A = *(unsigned long long*)&a;
    unsigned long long B = *(unsigned long long*)&b;
    unsigned long long C = *(unsigned long long*)&c;
    unsigned long long D;
    asm("fma.rn.f32x2 %0, %1, %2, %3;" : "=l"(D) : "l"(A), "l"(B), "l"(C));
    return *(float2*)&D;
}
__device__ __forceinline__ float2 fmul2(float2 a, float2 b) {
    unsigned long long A = *(unsigned long long*)&a;
    unsigned long long B = *(unsigned long long*)&b;
    unsigned long long D;
    asm("mul.rn.f32x2 %0, %1, %2;" : "=l"(D) : "l"(A), "l"(B));
    return *(float2*)&D;
}

// ---------------------------------------------------------------------------
// Kernel 1: fused data_bn (eval) + 1x1 qkv conv. 3 blocks per b (T split 100).
// (R6 version — proven fastest.)
// ---------------------------------------------------------------------------
__global__ void __launch_bounds__(256, 3) qkv_kernel(
    const float* __restrict__ x,
    const float* __restrict__ dg, const float* __restrict__ db,
    const float* __restrict__ dm, const float* __restrict__ dv,
    const float* __restrict__ W,  const float* __restrict__ Wb)
{
    int b = blockIdx.x;
    int T0 = blockIdx.y * 100;
    int n = b / Vv, v = b - n * Vv;
    extern __shared__ float sm[];
    float* xs = sm;             // 64*100
    float* Wt = xs + 6400;      // 12288  Wt[c*192+o] = W[o*64+c]
    float* sc = Wt + 12288;     // 64
    float* bi = sc + 64;        // 64
    int tid = threadIdx.x;

    if (tid < 64) {
        int idx = tid * Vv + v;
        float s = dg[idx] * rsqrtf(dv[idx] + 1e-5f);
        sc[tid] = s;
        bi[tid] = db[idx] - dm[idx] * s;
    }
    for (int i = tid; i < 192 * 64; i += 256) {
        int c = i / 192, o = i - c * 192;
        Wt[i] = W[o * 64 + c];
    }
    __syncthreads();

    const float* xb = x + ((size_t)n * Cc) * Tt * Vv + v;
    for (int i = tid; i < 64 * 100; i += 256) {
        int c = i / 100, tt = i - c * 100;
        xs[i] = xb[(size_t)(c * Tt + T0 + tt) * Vv] * sc[c] + bi[c];
    }
    __syncthreads();

    for (int tile = tid; tile < 1200; tile += 256) {
        int tg = tile / 48, og = tile - tg * 48;
        int o0 = og * 4, t0 = tg * 4;
        float acc[4][4] = {};
        #pragma unroll 8
        for (int c = 0; c < 64; ++c) {
            float4 w4 = *(const float4*)(Wt + c * 192 + o0);
            float4 x4 = *(const float4*)(xs + c * 100 + t0);
            float wa[4] = {w4.x, w4.y, w4.z, w4.w};
            float xa[4] = {x4.x, x4.y, x4.z, x4.w};
            #pragma unroll
            for (int i = 0; i < 4; ++i)
                #pragma unroll
                for (int j = 0; j < 4; ++j)
                    acc[i][j] += wa[i] * xa[j];
        }
        float* outp = g_qkv + ((size_t)b * QKVO + o0) * Tt + T0 + t0;
        #pragma unroll
        for (int i = 0; i < 4; ++i) {
            float bias = Wb[o0 + i];
            float scale = (o0 + i < 64) ? 0.25f : 1.0f;  // q * DKH^-0.5
            float4 r;
            r.x = (acc[i][0] + bias) * scale;
            r.y = (acc[i][1] + bias) * scale;
            r.z = (acc[i][2] + bias) * scale;
            r.w = (acc[i][3] + bias) * scale;
            *(float4*)(outp + i * Tt) = r;
        }
    }
}

// ---------------------------------------------------------------------------
// Kernel 2: attention per (b,h). 76,800B smem -> 3 CTAs/SM (exact fit).
// QK+softmax: R6 (ks in smem, register logits, f32x2).
// AV: R8 quarter-sweeps (16-reg acc) over vt[300][16] with sbase clamp.
// ---------------------------------------------------------------------------
#define KST 300   // ks row stride
#define RST 600   // krs row stride

__global__ void __launch_bounds__(256, 3) attn_kernel(const float* __restrict__ key_rel)
{
    int bh = blockIdx.x;
    int b = bh >> 2, h = bh & 3;
    extern __shared__ float sm[];
    float* ks  = sm;                   // 16*300  [d][s]
    float* krs = ks + 16 * KST;        // 16*600  [d][m]
    float* vt  = krs + 16 * RST;       // 300*16  [s][d] chunk-swizzled

    const float* base = g_qkv + (size_t)b * QKVO * Tt;
    const float* qg = base + (h * 16) * Tt;
    const float* kg = base + (64 + h * 16) * Tt;
    const float* vg = base + (128 + h * 16) * Tt;

    int tid = threadIdx.x;
    for (int i = tid; i < 1200; i += 256)
        ((float4*)ks)[i] = ((const float4*)kg)[i];
    for (int i = tid; i < 16 * RST; i += 256) {
        int d = i / RST, m = i - d * RST;
        krs[i] = (m <= 598) ? key_rel[m * 16 + d] : 0.f;
    }
    // vt fill: vt[s][d], 16B chunk c = d>>2 swizzled by (s>>2)&3 (300 rows)
    for (int i = tid; i < 4800; i += 256) {
        int d = i / 300, s = i - d * 300;
        int c = d >> 2, w = (s >> 2) & 3;
        vt[s * 16 + ((c ^ w) << 2) + (d & 3)] = vg[i];
    }
    __syncthreads();

    int warp = tid >> 5, lane = tid & 31;
    int lw = lane & 3;                         // vt swizzle key

    for (int g = warp; g < 75; g += 8) {
        int t0 = g * 4;
        float2 L[3][4][2];
        bool v2 = (lane < 11);
        #pragma unroll
        for (int p = 0; p < 3; ++p) {
            float init = (p < 2 || v2) ? 0.f : -1e30f;
            #pragma unroll
            for (int i = 0; i < 4; ++i) {
                L[p][i][0] = make_float2(init, init);
                L[p][i][1] = make_float2(init, init);
            }
        }

        // ---- QK + rel (packed over s-pairs) ----
        #pragma unroll
        for (int d = 0; d < 16; ++d) {
            float4 q4 = __ldg((const float4*)(qg + d * 300 + t0));
            float2 qd[4] = { make_float2(q4.x, q4.x), make_float2(q4.y, q4.y),
                             make_float2(q4.z, q4.z), make_float2(q4.w, q4.w) };
            #pragma unroll
            for (int p = 0; p < 3; ++p) {
                if (p < 2 || v2) {
                    int s0 = p * 128 + lane * 4;
                    int m0 = s0 - t0 + 296;            // >= 0, mod 4 == 0
                    float4 k4 = *(const float4*)(ks + d * KST + s0);
                    float4 ra = *(const float4*)(krs + d * RST + m0);
                    float4 rb = *(const float4*)(krs + d * RST + m0 + 4);
                    float2 k01 = make_float2(k4.x, k4.y), k23 = make_float2(k4.z, k4.w);
                    float2 r01 = make_float2(ra.x, ra.y), r23 = make_float2(ra.z, ra.w);
                    float2 r45 = make_float2(rb.x, rb.y);
                    float2 r12 = make_float2(ra.y, ra.z);
                    float2 r34 = make_float2(ra.w, rb.x);
                    float2 r56 = make_float2(rb.y, rb.z);
                    L[p][0][0] = ffma2(qd[0], k01, L[p][0][0]); L[p][0][1] = ffma2(qd[0], k23, L[p][0][1]);
                    L[p][1][0] = ffma2(qd[1], k01, L[p][1][0]); L[p][1][1] = ffma2(qd[1], k23, L[p][1][1]);
                    L[p][2][0] = ffma2(qd[2], k01, L[p][2][0]); L[p][2][1] = ffma2(qd[2], k23, L[p][2][1]);
                    L[p][3][0] = ffma2(qd[3], k01, L[p][3][0]); L[p][3][1] = ffma2(qd[3], k23, L[p][3][1]);
                    L[p][0][0] = ffma2(qd[0], r34, L[p][0][0]); L[p][0][1] = ffma2(qd[0], r56, L[p][0][1]);
                    L[p][1][0] = ffma2(qd[1], r23, L[p][1][0]); L[p][1][1] = ffma2(qd[1], r45, L[p][1][1]);
                    L[p][2][0] = ffma2(qd[2], r12, L[p][2][0]); L[p][2][1] = ffma2(qd[2], r34, L[p][2][1]);
                    L[p][3][0] = ffma2(qd[3], r01, L[p][3][0]); L[p][3][1] = ffma2(qd[3], r23, L[p][3][1]);
                }
            }
        }

        // ---- softmax per row ----
        #pragma unroll
        for (int i = 0; i < 4; ++i) {
            float mx = -1e30f;
            #pragma unroll
            for (int p = 0; p < 3; ++p)
                #pragma unroll
                for (int jp = 0; jp < 2; ++jp)
                    mx = fmaxf(mx, fmaxf(L[p][i][jp].x, L[p][i][jp].y));
            #pragma unroll
            for (int o = 16; o > 0; o >>= 1)
                mx = fmaxf(mx, __shfl_xor_sync(0xffffffffu, mx, o));
            float s = 0.f;
            #pragma unroll
            for (int p = 0; p < 3; ++p)
                #pragma unroll
                for (int jp = 0; jp < 2; ++jp) {
                    float ex = __expf(L[p][i][jp].x - mx);
                    float ey = __expf(L[p][i][jp].y - mx);
                    L[p][i][jp] = make_float2(ex, ey);
                    s += ex + ey;
                }
            #pragma unroll
            for (int o = 16; o > 0; o >>= 1)
                s += __shfl_xor_sync(0xffffffffu, s, o);
            float inv = 1.f / s;
            float2 inv2 = make_float2(inv, inv);
            #pragma unroll
            for (int p = 0; p < 3; ++p)
                #pragma unroll
                for (int jp = 0; jp < 2; ++jp)
                    L[p][i][jp] = fmul2(L[p][i][jp], inv2);
        }

        // ---- AV: 4 quarter-sweeps of 4 head-dims (16-reg accumulator) ----
        #pragma unroll
        for (int ch = 0; ch < 4; ++ch) {
            float2 r[8];   // r[i*2+c2]: partial out[t0+i][ch*4 + c2*2 .. +1]
            #pragma unroll
            for (int k = 0; k < 8; ++k) r[k] = make_float2(0.f, 0.f);

            #pragma unroll
            for (int p = 0; p < 3; ++p) {
                int sbase = p * 128 + lane * 4;
                if (sbase > 296) sbase = 296;     // invalid lanes: probs are 0
                #pragma unroll
                for (int j = 0; j < 4; ++j) {
                    const float* vp = vt + (sbase + j) * 16;
                    float4 va = *(const float4*)(vp + ((ch ^ lw) << 2));
                    float2 v01 = make_float2(va.x, va.y);
                    float2 v23 = make_float2(va.z, va.w);
                    #pragma unroll
                    for (int i = 0; i < 4; ++i) {
                        float pij = (j & 1) ? L[p][i][j >> 1].y : L[p][i][j >> 1].x;
                        float2 pp = make_float2(pij, pij);
                        r[i * 2 + 0] = ffma2(pp, v01, r[i * 2 + 0]);
                        r[i * 2 + 1] = ffma2(pp, v23, r[i * 2 + 1]);
                    }
                }
            }

            // select-merge butterfly: i1 <- bit4, i0 <- bit3, c2 <- bit2, dd0 <- bit1
            bool hi;
            hi = (lane & 16);
            #pragma unroll
            for (int k = 0; k < 4; ++k) {
                float2 keep = hi ? r[k + 4] : r[k];
                float2 send = hi ? r[k] : r[k + 4];
                keep.x += __shfl_xor_sync(0xffffffffu, send.x, 16);
                keep.y += __shfl_xor_sync(0xffffffffu, send.y, 16);
                r[k] = keep;
            }
            hi = (lane & 8);
            #pragma unroll
            for (int k = 0; k < 2; ++k) {
                float2 keep = hi ? r[k + 2] : r[k];
                float2 send = hi ? r[k] : r[k + 2];
                keep.x += __shfl_xor_sync(0xffffffffu, send.x, 8);
                keep.y += __shfl_xor_sync(0xffffffffu, send.y, 8);
                r[k] = keep;
            }
            hi = (lane & 4);
            {
                float2 keep = hi ? r[1] : r[0];
                float2 send = hi ? r[0] : r[1];
                keep.x += __shfl_xor_sync(0xffffffffu, send.x, 4);
                keep.y += __shfl_xor_sync(0xffffffffu, send.y, 4);
                r[0] = keep;
            }
            {
                bool hb = (lane & 2);
                float keep = hb ? r[0].y : r[0].x;
                float send = hb ? r[0].x : r[0].y;
                float val = keep + __shfl_xor_sync(0xffffffffu, send, 2);
                val += __shfl_xor_sync(0xffffffffu, val, 1);
                if (!(lane & 1)) {
                    int i  = (((lane >> 4) & 1) << 1) | ((lane >> 3) & 1);
                    int dd = (((lane >> 2) & 1) << 1) | ((lane >> 1) & 1);
                    int d = ch * 4 + dd;
                    g_attn[((size_t)b * 64 + h * 16 + d) * Tt + t0 + i] = val;
                }
            }
        }
    }
}

// ---------------------------------------------------------------------------
// Kernel 3: head-mix projection + skip + BN + ReLU — R6 version.
// ---------------------------------------------------------------------------
__global__ void __launch_bounds__(256, 4) proj_kernel(
    const float* __restrict__ Wa, const float* __restrict__ Ba,
    const float* __restrict__ bg, const float* __restrict__ bb,
    const float* __restrict__ bm, const float* __restrict__ bv,
    const float* __restrict__ x, float* __restrict__ out)
{
    int b = blockIdx.x;
    int half = blockIdx.y;
    int n = b / Vv, v = b - n * Vv;
    int T0 = half * 152;
    int TL = half ? 148 : 152;
    extern __shared__ float sm[];
    float* as = sm;            // 64*152
    float* Wt = as + 64 * 152; // 64*64
    float* s2 = Wt + 4096;     // 64
    float* b2 = s2 + 64;       // 64
    int tid = threadIdx.x;

    const float* ag = g_attn + (size_t)b * 64 * Tt;
    for (int i = tid; i < 64 * TL; i += 256) {
        int d = i / TL, tt = i - d * TL;
        as[d * 152 + tt] = ag[d * Tt + T0 + tt];
    }
    for (int i = tid; i < 4096; i += 256) {
        int d = i >> 6, o = i & 63;
        Wt[i] = Wa[o * 64 + d];
    }
    if (tid < 64) {
        float s = bg[tid] * rsqrtf(bv[tid] + 1e-5f);
        s2[tid] = s;
        b2[tid] = bb[tid] - bm[tid] * s;
    }
    __syncthreads();

    const float* xb = x + ((size_t)n * Cc) * Tt * Vv + v;
    float*       ob = out + ((size_t)n * Cc) * Tt * Vv + v;

    int tcols = TL >> 2;
    int ntile = 16 * tcols;
    for (int tile = tid; tile < ntile; tile += 256) {
        int og = tile & 15, tg = tile >> 4;
        int o0 = og * 4, t0 = tg * 4;
        float acc[4][4] = {};
        #pragma unroll 8
        for (int d = 0; d < 64; ++d) {
            float4 w4 = *(const float4*)(Wt + d * 64 + o0);
            float4 a4 = *(const float4*)(as + d * 152 + t0);
            float wa[4] = {w4.x, w4.y, w4.z, w4.w};
            float aa[4] = {a4.x, a4.y, a4.z, a4.w};
            #pragma unroll
            for (int i = 0; i < 4; ++i)
                #pragma unroll
                for (int j = 0; j < 4; ++j)
                    acc[i][j] += wa[i] * aa[j];
        }
        #pragma unroll
        for (int i = 0; i < 4; ++i) {
            int o = o0 + i;
            float bias = Ba[o];
            #pragma unroll
            for (int j = 0; j < 4; ++j) {
                int t = T0 + t0 + j;
                size_t gi = (size_t)(o * Tt + t) * Vv;
                float r = acc[i][j] + bias + xb[gi];
                r = r * s2[o] + b2[o];
                ob[gi] = fmaxf(r, 0.f);
            }
        }
    }
}

// ---------------------------------------------------------------------------
extern "C" void kernel_launch(void* const* d_in, const int* in_sizes, int n_in,
                              void* d_out, int out_size)
{
    const float* x       = (const float*)d_in[0];
    const float* dbn_g   = (const float*)d_in[1];
    const float* dbn_b   = (const float*)d_in[2];
    const float* dbn_m   = (const float*)d_in[3];
    const float* dbn_v   = (const float*)d_in[4];
    const float* qkv_w   = (const float*)d_in[5];
    const float* qkv_b   = (const float*)d_in[6];
    const float* key_rel = (const float*)d_in[7];
    const float* attn_w  = (const float*)d_in[8];
    const float* attn_b  = (const float*)d_in[9];
    const float* bn_g    = (const float*)d_in[10];
    const float* bn_b    = (const float*)d_in[11];
    const float* bn_m    = (const float*)d_in[12];
    const float* bn_v    = (const float*)d_in[13];
    float* out = (float*)d_out;

    const int SM1 = (6400 + 12288 + 128) * 4;              // 75,264
    const int SM2 = (16 * KST + 16 * RST + 300 * 16) * 4;  // 76,800
    const int SM3 = (64 * 152 + 4096 + 128) * 4;           // 55,808

    cudaFuncSetAttribute(qkv_kernel,  cudaFuncAttributeMaxDynamicSharedMemorySize, SM1);
    cudaFuncSetAttribute(attn_kernel, cudaFuncAttributeMaxDynamicSharedMemorySize, SM2);
    cudaFuncSetAttribute(proj_kernel, cudaFuncAttributeMaxDynamicSharedMemorySize, SM3);

    qkv_kernel<<<dim3(Bb, 3), 256, SM1>>>(x, dbn_g, dbn_b, dbn_m, dbn_v, qkv_w, qkv_b);
    attn_kernel<<<Bb * NHh, 256, SM2>>>(key_rel);
    proj_kernel<<<dim3(Bb, 2), 256, SM3>>>(attn_w, attn_b, bn_g, bn_b, bn_m, bn_v, x, out);
}

// round 11
// speedup vs baseline: 1.1395x; 1.1395x over previous
#include <cuda_runtime.h>
#include <cuda_bf16.h>
#include <math.h>

#define Nn 16
#define Cc 64
#define Tt 300
#define Vv 25
#define NHh 4
#define Bb (Nn*Vv)          // 400
#define QKVO 192            // 2*DK+DV

__device__ float g_qkv[(size_t)Bb * QKVO * Tt];
__device__ float g_attn[(size_t)Bb * 64 * Tt];

// ---- packed fp32 helpers (FFMA2 / FMUL2 are PTX-only on sm_103a) ----
__device__ __forceinline__ float2 ffma2(float2 a, float2 b, float2 c) {
    unsigned long long A = *(unsigned long long*)&a;
    unsigned long long B = *(unsigned long long*)&b;
    unsigned long long C = *(unsigned long long*)&c;
    unsigned long long D;
    asm("fma.rn.f32x2 %0, %1, %2, %3;" : "=l"(D) : "l"(A), "l"(B), "l"(C));
    return *(float2*)&D;
}
__device__ __forceinline__ float2 fmul2(float2 a, float2 b) {
    unsigned long long A = *(unsigned long long*)&a;
    unsigned long long B = *(unsigned long long*)&b;
    unsigned long long D;
    asm("mul.rn.f32x2 %0, %1, %2;" : "=l"(D) : "l"(A), "l"(B));
    return *(float2*)&D;
}

// ---------------------------------------------------------------------------
// Kernel 1: fused data_bn (eval) + 1x1 qkv conv. 3 blocks per b (T split 100).
// 4o x 8t register tile (2x ILP vs R6); 48 og x (12 full + 1 tail) tasks.
// ---------------------------------------------------------------------------
__global__ void __launch_bounds__(256, 3) qkv_kernel(
    const float* __restrict__ x,
    const float* __restrict__ dg, const float* __restrict__ db,
    const float* __restrict__ dm, const float* __restrict__ dv,
    const float* __restrict__ W,  const float* __restrict__ Wb)
{
    int b = blockIdx.x;
    int T0 = blockIdx.y * 100;
    int n = b / Vv, v = b - n * Vv;
    extern __shared__ float sm[];
    float* xs = sm;             // 64*100
    float* Wt = xs + 6400;      // 12288  Wt[c*192+o] = W[o*64+c]
    float* sc = Wt + 12288;     // 64
    float* bi = sc + 64;        // 64
    int tid = threadIdx.x;

    if (tid < 64) {
        int idx = tid * Vv + v;
        float s = dg[idx] * rsqrtf(dv[idx] + 1e-5f);
        sc[tid] = s;
        bi[tid] = db[idx] - dm[idx] * s;
    }
    for (int i = tid; i < 192 * 64; i += 256) {
        int c = i / 192, o = i - c * 192;
        Wt[i] = W[o * 64 + c];
    }
    __syncthreads();

    const float* xb = x + ((size_t)n * Cc) * Tt * Vv + v;
    for (int i = tid; i < 64 * 100; i += 256) {
        int c = i / 100, tt = i - c * 100;
        xs[i] = xb[(size_t)(c * Tt + T0 + tt) * Vv] * sc[c] + bi[c];
    }
    __syncthreads();

    // 624 tasks: og = task % 48 (fastest), tg = task / 48; t0 = tg*8.
    // tg < 12: 8-wide; tg == 12: 4-wide tail (t 96..99).
    for (int task = tid; task < 624; task += 256) {
        int og = task % 48, tg = task / 48;
        int o0 = og * 4, t0 = tg * 8;
        bool full = (tg < 12);
        float acc[4][8];
        #pragma unroll
        for (int i = 0; i < 4; ++i)
            #pragma unroll
            for (int j = 0; j < 8; ++j) acc[i][j] = 0.f;

        if (full) {
            #pragma unroll 8
            for (int c = 0; c < 64; ++c) {
                float4 w4 = *(const float4*)(Wt + c * 192 + o0);
                float4 xa = *(const float4*)(xs + c * 100 + t0);
                float4 xc = *(const float4*)(xs + c * 100 + t0 + 4);
                float wa[4] = {w4.x, w4.y, w4.z, w4.w};
                float A[8] = {xa.x, xa.y, xa.z, xa.w, xc.x, xc.y, xc.z, xc.w};
                #pragma unroll
                for (int i = 0; i < 4; ++i)
                    #pragma unroll
                    for (int j = 0; j < 8; ++j)
                        acc[i][j] += wa[i] * A[j];
            }
        } else {
            #pragma unroll 8
            for (int c = 0; c < 64; ++c) {
                float4 w4 = *(const float4*)(Wt + c * 192 + o0);
                float4 xa = *(const float4*)(xs + c * 100 + t0);
                float wa[4] = {w4.x, w4.y, w4.z, w4.w};
                float A[4] = {xa.x, xa.y, xa.z, xa.w};
                #pragma unroll
                for (int i = 0; i < 4; ++i)
                    #pragma unroll
                    for (int j = 0; j < 4; ++j)
                        acc[i][j] += wa[i] * A[j];
            }
        }

        float* outp = g_qkv + ((size_t)b * QKVO + o0) * Tt + T0 + t0;
        #pragma unroll
        for (int i = 0; i < 4; ++i) {
            float bias = Wb[o0 + i];
            float scale = (o0 + i < 64) ? 0.25f : 1.0f;  // q * DKH^-0.5
            float4 r;
            r.x = (acc[i][0] + bias) * scale;
            r.y = (acc[i][1] + bias) * scale;
            r.z = (acc[i][2] + bias) * scale;
            r.w = (acc[i][3] + bias) * scale;
            *(float4*)(outp + i * Tt) = r;
            if (full) {
                float4 r2;
                r2.x = (acc[i][4] + bias) * scale;
                r2.y = (acc[i][5] + bias) * scale;
                r2.z = (acc[i][6] + bias) * scale;
                r2.w = (acc[i][7] + bias) * scale;
                *(float4*)(outp + i * Tt + 4) = r2;
            }
        }
    }
}

// ---------------------------------------------------------------------------
// Kernel 2: attention per (b,h) — R6 version VERBATIM (proven 615us).
// ---------------------------------------------------------------------------
#define KST 300   // ks row stride
#define RST 600   // krs row stride

__global__ void __launch_bounds__(256, 2) attn_kernel(const float* __restrict__ key_rel)
{
    int bh = blockIdx.x;
    int b = bh >> 2, h = bh & 3;
    extern __shared__ float sm[];
    float* ks   = sm;                  // 16*300  [d][s]
    float* krs  = ks + 16 * KST;       // 16*600  [d][m]
    float* vt   = krs + 16 * RST;      // 384*16  [s][d] chunk-swizzled

    const float* base = g_qkv + (size_t)b * QKVO * Tt;
    const float* qg = base + (h * 16) * Tt;
    const float* kg = base + (64 + h * 16) * Tt;
    const float* vg = base + (128 + h * 16) * Tt;

    int tid = threadIdx.x;
    for (int i = tid; i < 1200; i += 256)
        ((float4*)ks)[i] = ((const float4*)kg)[i];
    for (int i = tid; i < 599 * 16; i += 256) {
        int m = i >> 4, d = i & 15;
        krs[d * RST + m] = key_rel[i];
    }
    for (int i = tid + 4800; i < 6144; i += 256)
        vt[i] = 0.f;
    for (int i = tid; i < 4800; i += 256) {
        int d = i / 300, s = i - d * 300;
        int c = d >> 2, w = (s >> 2) & 3;
        vt[s * 16 + ((c ^ w) << 2) + (d & 3)] = vg[i];
    }
    __syncthreads();

    int warp = tid >> 5, lane = tid & 31;
    int lw = lane & 3;
    int oi = (((lane >> 4) & 1) << 1) | ((lane >> 3) & 1);
    int odp = (((lane >> 2) & 1) << 1) | ((lane >> 1) & 1);
    int odb = lane & 1;

    for (int g = warp; g < 75; g += 8) {
        int t0 = g * 4;
        float2 L[3][4][2];
        bool v2 = (lane < 11);
        #pragma unroll
        for (int p = 0; p < 3; ++p) {
            float init = (p < 2 || v2) ? 0.f : -1e30f;
            #pragma unroll
            for (int i = 0; i < 4; ++i) {
                L[p][i][0] = make_float2(init, init);
                L[p][i][1] = make_float2(init, init);
            }
        }

        #pragma unroll
        for (int d = 0; d < 16; ++d) {
            float4 q4 = __ldg((const float4*)(qg + d * 300 + t0));
            float2 qd[4] = { make_float2(q4.x, q4.x), make_float2(q4.y, q4.y),
                             make_float2(q4.z, q4.z), make_float2(q4.w, q4.w) };
            #pragma unroll
            for (int p = 0; p < 3; ++p) {
                if (p < 2 || v2) {
                    int s0 = p * 128 + lane * 4;
                    int m0 = s0 - t0 + 296;
                    float4 k4 = *(const float4*)(ks + d * KST + s0);
                    float4 ra = *(const float4*)(krs + d * RST + m0);
                    float4 rb = *(const float4*)(krs + d * RST + m0 + 4);
                    float2 k01 = make_float2(k4.x, k4.y), k23 = make_float2(k4.z, k4.w);
                    float2 r01 = make_float2(ra.x, ra.y), r23 = make_float2(ra.z, ra.w);
                    float2 r45 = make_float2(rb.x, rb.y);
                    float2 r12 = make_float2(ra.y, ra.z);
                    float2 r34 = make_float2(ra.w, rb.x);
                    float2 r56 = make_float2(rb.y, rb.z);
                    L[p][0][0] = ffma2(qd[0], k01, L[p][0][0]); L[p][0][1] = ffma2(qd[0], k23, L[p][0][1]);
                    L[p][1][0] = ffma2(qd[1], k01, L[p][1][0]); L[p][1][1] = ffma2(qd[1], k23, L[p][1][1]);
                    L[p][2][0] = ffma2(qd[2], k01, L[p][2][0]); L[p][2][1] = ffma2(qd[2], k23, L[p][2][1]);
                    L[p][3][0] = ffma2(qd[3], k01, L[p][3][0]); L[p][3][1] = ffma2(qd[3], k23, L[p][3][1]);
                    L[p][0][0] = ffma2(qd[0], r34, L[p][0][0]); L[p][0][1] = ffma2(qd[0], r56, L[p][0][1]);
                    L[p][1][0] = ffma2(qd[1], r23, L[p][1][0]); L[p][1][1] = ffma2(qd[1], r45, L[p][1][1]);
                    L[p][2][0] = ffma2(qd[2], r12, L[p][2][0]); L[p][2][1] = ffma2(qd[2], r34, L[p][2][1]);
                    L[p][3][0] = ffma2(qd[3], r01, L[p][3][0]); L[p][3][1] = ffma2(qd[3], r23, L[p][3][1]);
                }
            }
        }

        #pragma unroll
        for (int i = 0; i < 4; ++i) {
            float mx = -1e30f;
            #pragma unroll
            for (int p = 0; p < 3; ++p)
                #pragma unroll
                for (int jp = 0; jp < 2; ++jp)
                    mx = fmaxf(mx, fmaxf(L[p][i][jp].x, L[p][i][jp].y));
            #pragma unroll
            for (int o = 16; o > 0; o >>= 1)
                mx = fmaxf(mx, __shfl_xor_sync(0xffffffffu, mx, o));
            float s = 0.f;
            #pragma unroll
            for (int p = 0; p < 3; ++p)
                #pragma unroll
                for (int jp = 0; jp < 2; ++jp) {
                    float ex = __expf(L[p][i][jp].x - mx);
                    float ey = __expf(L[p][i][jp].y - mx);
                    L[p][i][jp] = make_float2(ex, ey);
                    s += ex + ey;
                }
            #pragma unroll
            for (int o = 16; o > 0; o >>= 1)
                s += __shfl_xor_sync(0xffffffffu, s, o);
            float inv = 1.f / s;
            float2 inv2 = make_float2(inv, inv);
            #pragma unroll
            for (int p = 0; p < 3; ++p)
                #pragma unroll
                for (int jp = 0; jp < 2; ++jp)
                    L[p][i][jp] = fmul2(L[p][i][jp], inv2);
        }

        #pragma unroll
        for (int sweep = 0; sweep < 2; ++sweep) {
            float2 r[16];
            #pragma unroll
            for (int k = 0; k < 16; ++k) r[k] = make_float2(0.f, 0.f);

            #pragma unroll
            for (int p = 0; p < 3; ++p) {
                int sbase = p * 128 + lane * 4;
                #pragma unroll
                for (int j = 0; j < 4; ++j) {
                    const float* vp = vt + (sbase + j) * 16;
                    float4 va = *(const float4*)(vp + (((sweep * 2)     ^ lw) << 2));
                    float4 vb = *(const float4*)(vp + (((sweep * 2 + 1) ^ lw) << 2));
                    float2 v01 = make_float2(va.x, va.y);
                    float2 v23 = make_float2(va.z, va.w);
                    float2 v45 = make_float2(vb.x, vb.y);
                    float2 v67 = make_float2(vb.z, vb.w);
                    #pragma unroll
                    for (int i = 0; i < 4; ++i) {
                        float pij = (j & 1) ? L[p][i][j >> 1].y : L[p][i][j >> 1].x;
                        float2 pp = make_float2(pij, pij);
                        r[i * 4 + 0] = ffma2(pp, v01, r[i * 4 + 0]);
                        r[i * 4 + 1] = ffma2(pp, v23, r[i * 4 + 1]);
                        r[i * 4 + 2] = ffma2(pp, v45, r[i * 4 + 2]);
                        r[i * 4 + 3] = ffma2(pp, v67, r[i * 4 + 3]);
                    }
                }
            }

            bool hi;
            hi = (lane & 16);
            #pragma unroll
            for (int k = 0; k < 8; ++k) {
                float2 keep = hi ? r[k + 8] : r[k];
                float2 send = hi ? r[k] : r[k + 8];
                keep.x += __shfl_xor_sync(0xffffffffu, send.x, 16);
                keep.y += __shfl_xor_sync(0xffffffffu, send.y, 16);
                r[k] = keep;
            }
            hi = (lane & 8);
            #pragma unroll
            for (int k = 0; k < 4; ++k) {
                float2 keep = hi ? r[k + 4] : r[k];
                float2 send = hi ? r[k] : r[k + 4];
                keep.x += __shfl_xor_sync(0xffffffffu, send.x, 8);
                keep.y += __shfl_xor_sync(0xffffffffu, send.y, 8);
                r[k] = keep;
            }
            hi = (lane & 4);
            #pragma unroll
            for (int k = 0; k < 2; ++k) {
                float2 keep = hi ? r[k + 2] : r[k];
                float2 send = hi ? r[k] : r[k + 2];
                keep.x += __shfl_xor_sync(0xffffffffu, send.x, 4);
                keep.y += __shfl_xor_sync(0xffffffffu, send.y, 4);
                r[k] = keep;
            }
            hi = (lane & 2);
            {
                float2 keep = hi ? r[1] : r[0];
                float2 send = hi ? r[0] : r[1];
                keep.x += __shfl_xor_sync(0xffffffffu, send.x, 2);
                keep.y += __shfl_xor_sync(0xffffffffu, send.y, 2);
                r[0] = keep;
            }
            {
                bool hb = (lane & 1);
                float keep = hb ? r[0].y : r[0].x;
                float send = hb ? r[0].x : r[0].y;
                float outv = keep + __shfl_xor_sync(0xffffffffu, send, 1);
                int d = sweep * 8 + odp * 2 + odb;
                g_attn[((size_t)b * 64 + h * 16 + d) * Tt + t0 + oi] = outv;
            }
        }
    }
}

// ---------------------------------------------------------------------------
// Kernel 3: head-mix projection + skip + BN + ReLU. 2 blocks per b (T split).
// 4o x 8t register tile (152 = 19*8, no tail).
// ---------------------------------------------------------------------------
__global__ void __launch_bounds__(256, 3) proj_kernel(
    const float* __restrict__ Wa, const float* __restrict__ Ba,
    const float* __restrict__ bg, const float* __restrict__ bb,
    const float* __restrict__ bm, const float* __restrict__ bv,
    const float* __restrict__ x, float* __restrict__ out)
{
    int b = blockIdx.x;
    int half = blockIdx.y;
    int n = b / Vv, v = b - n * Vv;
    int T0 = half * 152;
    int TL = half ? 148 : 152;
    extern __shared__ float sm[];
    float* as = sm;            // 64*152
    float* Wt = as + 64 * 152; // 64*64
    float* s2 = Wt + 4096;     // 64
    float* b2 = s2 + 64;       // 64
    int tid = threadIdx.x;

    const float* ag = g_attn + (size_t)b * 64 * Tt;
    for (int i = tid; i < 64 * TL; i += 256) {
        int d = i / TL, tt = i - d * TL;
        as[d * 152 + tt] = ag[d * Tt + T0 + tt];
    }
    if (half) {  // zero pad tail columns 148..151 so 8-wide tiles read zeros
        for (int i = tid; i < 64 * 4; i += 256) {
            int d = i >> 2, tt = 148 + (i & 3);
            as[d * 152 + tt] = 0.f;
        }
    }
    for (int i = tid; i < 4096; i += 256) {
        int d = i >> 6, o = i & 63;
        Wt[i] = Wa[o * 64 + d];
    }
    if (tid < 64) {
        float s = bg[tid] * rsqrtf(bv[tid] + 1e-5f);
        s2[tid] = s;
        b2[tid] = bb[tid] - bm[tid] * s;
    }
    __syncthreads();

    const float* xb = x + ((size_t)n * Cc) * Tt * Vv + v;
    float*       ob = out + ((size_t)n * Cc) * Tt * Vv + v;

    // 304 tasks: og = task % 16 (fastest), tg = task / 16; t0 = tg*8
    for (int task = tid; task < 304; task += 256) {
        int og = task & 15, tg = task >> 4;
        int o0 = og * 4, t0 = tg * 8;
        float acc[4][8];
        #pragma unroll
        for (int i = 0; i < 4; ++i)
            #pragma unroll
            for (int j = 0; j < 8; ++j) acc[i][j] = 0.f;

        #pragma unroll 8
        for (int d = 0; d < 64; ++d) {
            float4 w4 = *(const float4*)(Wt + d * 64 + o0);
            float4 aa = *(const float4*)(as + d * 152 + t0);
            float4 ac = *(const float4*)(as + d * 152 + t0 + 4);
            float wa[4] = {w4.x, w4.y, w4.z, w4.w};
            float A[8] = {aa.x, aa.y, aa.z, aa.w, ac.x, ac.y, ac.z, ac.w};
            #pragma unroll
            for (int i = 0; i < 4; ++i)
                #pragma unroll
                for (int j = 0; j < 8; ++j)
                    acc[i][j] += wa[i] * A[j];
        }
        int tmax = TL - t0;   // 8 normally; 4 for last tile of half==1
        #pragma unroll
        for (int i = 0; i < 4; ++i) {
            int o = o0 + i;
            float bias = Ba[o];
            #pragma unroll
            for (int j = 0; j < 8; ++j) {
                if (j < tmax) {
                    int t = T0 + t0 + j;
                    size_t gi = (size_t)(o * Tt + t) * Vv;
                    float r = acc[i][j] + bias + xb[gi];
                    r = r * s2[o] + b2[o];
                    ob[gi] = fmaxf(r, 0.f);
                }
            }
        }
    }
}

// ---------------------------------------------------------------------------
extern "C" void kernel_launch(void* const* d_in, const int* in_sizes, int n_in,
                              void* d_out, int out_size)
{
    const float* x       = (const float*)d_in[0];
    const float* dbn_g   = (const float*)d_in[1];
    const float* dbn_b   = (const float*)d_in[2];
    const float* dbn_m   = (const float*)d_in[3];
    const float* dbn_v   = (const float*)d_in[4];
    const float* qkv_w   = (const float*)d_in[5];
    const float* qkv_b   = (const float*)d_in[6];
    const float* key_rel = (const float*)d_in[7];
    const float* attn_w  = (const float*)d_in[8];
    const float* attn_b  = (const float*)d_in[9];
    const float* bn_g    = (const float*)d_in[10];
    const float* bn_b    = (const float*)d_in[11];
    const float* bn_m    = (const float*)d_in[12];
    const float* bn_v    = (const float*)d_in[13];
    float* out = (float*)d_out;

    const int SM1 = (6400 + 12288 + 128) * 4;              // 75,264
    const int SM2 = (16 * KST + 16 * RST + 384 * 16) * 4;  // 82,176
    const int SM3 = (64 * 152 + 4096 + 128) * 4;           // 55,808

    cudaFuncSetAttribute(qkv_kernel,  cudaFuncAttributeMaxDynamicSharedMemorySize, SM1);
    cudaFuncSetAttribute(attn_kernel, cudaFuncAttributeMaxDynamicSharedMemorySize, SM2);
    cudaFuncSetAttribute(proj_kernel, cudaFuncAttributeMaxDynamicSharedMemorySize, SM3);

    qkv_kernel<<<dim3(Bb, 3), 256, SM1>>>(x, dbn_g, dbn_b, dbn_m, dbn_v, qkv_w, qkv_b);
    attn_kernel<<<Bb * NHh, 256, SM2>>>(key_rel);
    proj_kernel<<<dim3(Bb, 2), 256, SM3>>>(attn_w, attn_b, bn_g, bn_b, bn_m, bn_v, x, out);
}

// round 12
// speedup vs baseline: 1.2479x; 1.0951x over previous
#include <cuda_runtime.h>
#include <cuda_bf16.h>
#include <math.h>

#define Nn 16
#define Cc 64
#define Tt 300
#define Vv 25
#define NHh 4
#define Bb (Nn*Vv)          // 400
#define QKVO 192            // 2*DK+DV

__device__ float g_qkv[(size_t)Bb * QKVO * Tt];
__device__ float g_attn[(size_t)Bb * 64 * Tt];
__device__ float g_krt[16 * 600];   // key_rel transposed+padded, [d][m]
__device__ float g_Wt[64 * 192];    // qkv_w transposed, [c][o]
__device__ float g_Wat[64 * 64];    // attn_w transposed, [d][o]

// ---- packed fp32 helpers (FFMA2 / FMUL2 are PTX-only on sm_103a) ----
__device__ __forceinline__ float2 ffma2(float2 a, float2 b, float2 c) {
    unsigned long long A = *(unsigned long long*)&a;
    unsigned long long B = *(unsigned long long*)&b;
    unsigned long long C = *(unsigned long long*)&c;
    unsigned long long D;
    asm("fma.rn.f32x2 %0, %1, %2, %3;" : "=l"(D) : "l"(A), "l"(B), "l"(C));
    return *(float2*)&D;
}
__device__ __forceinline__ float2 fmul2(float2 a, float2 b) {
    unsigned long long A = *(unsigned long long*)&a;
    unsigned long long B = *(unsigned long long*)&b;
    unsigned long long D;
    asm("mul.rn.f32x2 %0, %1, %2;" : "=l"(D) : "l"(A), "l"(B));
    return *(float2*)&D;
}

// ---------------------------------------------------------------------------
// Kernel 0: one-time transposes (block-invariant data).
// ---------------------------------------------------------------------------
__global__ void prep_kernel(const float* __restrict__ key_rel,
                            const float* __restrict__ W,
                            const float* __restrict__ Wa)
{
    int tid = blockIdx.x * 256 + threadIdx.x;
    int stride = gridDim.x * 256;
    for (int i = tid; i < 16 * 600; i += stride) {
        int d = i / 600, m = i - d * 600;
        g_krt[i] = (m <= 598) ? key_rel[m * 16 + d] : 0.f;
    }
    for (int i = tid; i < 64 * 192; i += stride) {
        int c = i / 192, o = i - c * 192;
        g_Wt[i] = W[o * 64 + c];
    }
    for (int i = tid; i < 64 * 64; i += stride) {
        int d = i >> 6, o = i & 63;
        g_Wat[i] = Wa[o * 64 + d];
    }
}

// ---------------------------------------------------------------------------
// Kernel 1: fused data_bn (eval) + 1x1 qkv conv. 3 blocks per b (T split 100).
// 4o x 8t register tile; Wt filled by float4 copy from g_Wt.
// ---------------------------------------------------------------------------
__global__ void __launch_bounds__(256, 3) qkv_kernel(
    const float* __restrict__ x,
    const float* __restrict__ dg, const float* __restrict__ db,
    const float* __restrict__ dm, const float* __restrict__ dv,
    const float* __restrict__ Wb)
{
    int b = blockIdx.x;
    int T0 = blockIdx.y * 100;
    int n = b / Vv, v = b - n * Vv;
    extern __shared__ float sm[];
    float* xs = sm;             // 64*100
    float* Wt = xs + 6400;      // 12288  [c][o]
    float* sc = Wt + 12288;     // 64
    float* bi = sc + 64;        // 64
    int tid = threadIdx.x;

    if (tid < 64) {
        int idx = tid * Vv + v;
        float s = dg[idx] * rsqrtf(dv[idx] + 1e-5f);
        sc[tid] = s;
        bi[tid] = db[idx] - dm[idx] * s;
    }
    for (int i = tid; i < 3072; i += 256)
        ((float4*)Wt)[i] = ((const float4*)g_Wt)[i];
    __syncthreads();

    const float* xb = x + ((size_t)n * Cc) * Tt * Vv + v;
    for (int i = tid; i < 64 * 100; i += 256) {
        int c = i / 100, tt = i - c * 100;
        xs[i] = xb[(size_t)(c * Tt + T0 + tt) * Vv] * sc[c] + bi[c];
    }
    __syncthreads();

    // 624 tasks: og = task % 48, tg = task / 48; t0 = tg*8; tg==12 is 4-wide tail
    for (int task = tid; task < 624; task += 256) {
        int og = task % 48, tg = task / 48;
        int o0 = og * 4, t0 = tg * 8;
        bool full = (tg < 12);
        float acc[4][8];
        #pragma unroll
        for (int i = 0; i < 4; ++i)
            #pragma unroll
            for (int j = 0; j < 8; ++j) acc[i][j] = 0.f;

        if (full) {
            #pragma unroll 8
            for (int c = 0; c < 64; ++c) {
                float4 w4 = *(const float4*)(Wt + c * 192 + o0);
                float4 xa = *(const float4*)(xs + c * 100 + t0);
                float4 xc = *(const float4*)(xs + c * 100 + t0 + 4);
                float wa[4] = {w4.x, w4.y, w4.z, w4.w};
                float A[8] = {xa.x, xa.y, xa.z, xa.w, xc.x, xc.y, xc.z, xc.w};
                #pragma unroll
                for (int i = 0; i < 4; ++i)
                    #pragma unroll
                    for (int j = 0; j < 8; ++j)
                        acc[i][j] += wa[i] * A[j];
            }
        } else {
            #pragma unroll 8
            for (int c = 0; c < 64; ++c) {
                float4 w4 = *(const float4*)(Wt + c * 192 + o0);
                float4 xa = *(const float4*)(xs + c * 100 + t0);
                float wa[4] = {w4.x, w4.y, w4.z, w4.w};
                float A[4] = {xa.x, xa.y, xa.z, xa.w};
                #pragma unroll
                for (int i = 0; i < 4; ++i)
                    #pragma unroll
                    for (int j = 0; j < 4; ++j)
                        acc[i][j] += wa[i] * A[j];
            }
        }

        float* outp = g_qkv + ((size_t)b * QKVO + o0) * Tt + T0 + t0;
        #pragma unroll
        for (int i = 0; i < 4; ++i) {
            float bias = Wb[o0 + i];
            float scale = (o0 + i < 64) ? 0.25f : 1.0f;  // q * DKH^-0.5
            float4 r;
            r.x = (acc[i][0] + bias) * scale;
            r.y = (acc[i][1] + bias) * scale;
            r.z = (acc[i][2] + bias) * scale;
            r.w = (acc[i][3] + bias) * scale;
            *(float4*)(outp + i * Tt) = r;
            if (full) {
                float4 r2;
                r2.x = (acc[i][4] + bias) * scale;
                r2.y = (acc[i][5] + bias) * scale;
                r2.z = (acc[i][6] + bias) * scale;
                r2.w = (acc[i][7] + bias) * scale;
                *(float4*)(outp + i * Tt + 4) = r2;
            }
        }
    }
}

// ---------------------------------------------------------------------------
// Kernel 2: attention per (b,h) — R6 core; krs filled by float4 copy from
// g_krt; vt filled with STS.128 (same swizzle).
// ---------------------------------------------------------------------------
#define KST 300   // ks row stride
#define RST 600   // krs row stride

__global__ void __launch_bounds__(256, 2) attn_kernel()
{
    int bh = blockIdx.x;
    int b = bh >> 2, h = bh & 3;
    extern __shared__ float sm[];
    float* ks   = sm;                  // 16*300  [d][s]
    float* krs  = ks + 16 * KST;       // 16*600  [d][m]
    float* vt   = krs + 16 * RST;      // 384*16  [s][d] chunk-swizzled

    const float* base = g_qkv + (size_t)b * QKVO * Tt;
    const float* qg = base + (h * 16) * Tt;
    const float* kg = base + (64 + h * 16) * Tt;
    const float* vg = base + (128 + h * 16) * Tt;

    int tid = threadIdx.x;
    for (int i = tid; i < 1200; i += 256)
        ((float4*)ks)[i] = ((const float4*)kg)[i];
    for (int i = tid; i < 2400; i += 256)
        ((float4*)krs)[i] = ((const float4*)g_krt)[i];
    for (int i = tid + 4800; i < 6144; i += 256)
        vt[i] = 0.f;
    // vt fill: one float4 (4 d-values) per (s, chunk c), swizzled by (s>>2)&3
    for (int i = tid; i < 1200; i += 256) {
        int s = i >> 2, c = i & 3;
        int w = (s >> 2) & 3;
        float4 vv;
        vv.x = vg[(c * 4 + 0) * 300 + s];
        vv.y = vg[(c * 4 + 1) * 300 + s];
        vv.z = vg[(c * 4 + 2) * 300 + s];
        vv.w = vg[(c * 4 + 3) * 300 + s];
        *(float4*)(vt + s * 16 + ((c ^ w) << 2)) = vv;
    }
    __syncthreads();

    int warp = tid >> 5, lane = tid & 31;
    int lw = lane & 3;
    int oi = (((lane >> 4) & 1) << 1) | ((lane >> 3) & 1);
    int odp = (((lane >> 2) & 1) << 1) | ((lane >> 1) & 1);
    int odb = lane & 1;

    for (int g = warp; g < 75; g += 8) {
        int t0 = g * 4;
        float2 L[3][4][2];
        bool v2 = (lane < 11);
        #pragma unroll
        for (int p = 0; p < 3; ++p) {
            float init = (p < 2 || v2) ? 0.f : -1e30f;
            #pragma unroll
            for (int i = 0; i < 4; ++i) {
                L[p][i][0] = make_float2(init, init);
                L[p][i][1] = make_float2(init, init);
            }
        }

        #pragma unroll
        for (int d = 0; d < 16; ++d) {
            float4 q4 = __ldg((const float4*)(qg + d * 300 + t0));
            float2 qd[4] = { make_float2(q4.x, q4.x), make_float2(q4.y, q4.y),
                             make_float2(q4.z, q4.z), make_float2(q4.w, q4.w) };
            #pragma unroll
            for (int p = 0; p < 3; ++p) {
                if (p < 2 || v2) {
                    int s0 = p * 128 + lane * 4;
                    int m0 = s0 - t0 + 296;
                    float4 k4 = *(const float4*)(ks + d * KST + s0);
                    float4 ra = *(const float4*)(krs + d * RST + m0);
                    float4 rb = *(const float4*)(krs + d * RST + m0 + 4);
                    float2 k01 = make_float2(k4.x, k4.y), k23 = make_float2(k4.z, k4.w);
                    float2 r01 = make_float2(ra.x, ra.y), r23 = make_float2(ra.z, ra.w);
                    float2 r45 = make_float2(rb.x, rb.y);
                    float2 r12 = make_float2(ra.y, ra.z);
                    float2 r34 = make_float2(ra.w, rb.x);
                    float2 r56 = make_float2(rb.y, rb.z);
                    L[p][0][0] = ffma2(qd[0], k01, L[p][0][0]); L[p][0][1] = ffma2(qd[0], k23, L[p][0][1]);
                    L[p][1][0] = ffma2(qd[1], k01, L[p][1][0]); L[p][1][1] = ffma2(qd[1], k23, L[p][1][1]);
                    L[p][2][0] = ffma2(qd[2], k01, L[p][2][0]); L[p][2][1] = ffma2(qd[2], k23, L[p][2][1]);
                    L[p][3][0] = ffma2(qd[3], k01, L[p][3][0]); L[p][3][1] = ffma2(qd[3], k23, L[p][3][1]);
                    L[p][0][0] = ffma2(qd[0], r34, L[p][0][0]); L[p][0][1] = ffma2(qd[0], r56, L[p][0][1]);
                    L[p][1][0] = ffma2(qd[1], r23, L[p][1][0]); L[p][1][1] = ffma2(qd[1], r45, L[p][1][1]);
                    L[p][2][0] = ffma2(qd[2], r12, L[p][2][0]); L[p][2][1] = ffma2(qd[2], r34, L[p][2][1]);
                    L[p][3][0] = ffma2(qd[3], r01, L[p][3][0]); L[p][3][1] = ffma2(qd[3], r23, L[p][3][1]);
                }
            }
        }

        #pragma unroll
        for (int i = 0; i < 4; ++i) {
            float mx = -1e30f;
            #pragma unroll
            for (int p = 0; p < 3; ++p)
                #pragma unroll
                for (int jp = 0; jp < 2; ++jp)
                    mx = fmaxf(mx, fmaxf(L[p][i][jp].x, L[p][i][jp].y));
            #pragma unroll
            for (int o = 16; o > 0; o >>= 1)
                mx = fmaxf(mx, __shfl_xor_sync(0xffffffffu, mx, o));
            float s = 0.f;
            #pragma unroll
            for (int p = 0; p < 3; ++p)
                #pragma unroll
                for (int jp = 0; jp < 2; ++jp) {
                    float ex = __expf(L[p][i][jp].x - mx);
                    float ey = __expf(L[p][i][jp].y - mx);
                    L[p][i][jp] = make_float2(ex, ey);
                    s += ex + ey;
                }
            #pragma unroll
            for (int o = 16; o > 0; o >>= 1)
                s += __shfl_xor_sync(0xffffffffu, s, o);
            float inv = 1.f / s;
            float2 inv2 = make_float2(inv, inv);
            #pragma unroll
            for (int p = 0; p < 3; ++p)
                #pragma unroll
                for (int jp = 0; jp < 2; ++jp)
                    L[p][i][jp] = fmul2(L[p][i][jp], inv2);
        }

        #pragma unroll
        for (int sweep = 0; sweep < 2; ++sweep) {
            float2 r[16];
            #pragma unroll
            for (int k = 0; k < 16; ++k) r[k] = make_float2(0.f, 0.f);

            #pragma unroll
            for (int p = 0; p < 3; ++p) {
                int sbase = p * 128 + lane * 4;
                #pragma unroll
                for (int j = 0; j < 4; ++j) {
                    const float* vp = vt + (sbase + j) * 16;
                    float4 va = *(const float4*)(vp + (((sweep * 2)     ^ lw) << 2));
                    float4 vb = *(const float4*)(vp + (((sweep * 2 + 1) ^ lw) << 2));
                    float2 v01 = make_float2(va.x, va.y);
                    float2 v23 = make_float2(va.z, va.w);
                    float2 v45 = make_float2(vb.x, vb.y);
                    float2 v67 = make_float2(vb.z, vb.w);
                    #pragma unroll
                    for (int i = 0; i < 4; ++i) {
                        float pij = (j & 1) ? L[p][i][j >> 1].y : L[p][i][j >> 1].x;
                        float2 pp = make_float2(pij, pij);
                        r[i * 4 + 0] = ffma2(pp, v01, r[i * 4 + 0]);
                        r[i * 4 + 1] = ffma2(pp, v23, r[i * 4 + 1]);
                        r[i * 4 + 2] = ffma2(pp, v45, r[i * 4 + 2]);
                        r[i * 4 + 3] = ffma2(pp, v67, r[i * 4 + 3]);
                    }
                }
            }

            bool hi;
            hi = (lane & 16);
            #pragma unroll
            for (int k = 0; k < 8; ++k) {
                float2 keep = hi ? r[k + 8] : r[k];
                float2 send = hi ? r[k] : r[k + 8];
                keep.x += __shfl_xor_sync(0xffffffffu, send.x, 16);
                keep.y += __shfl_xor_sync(0xffffffffu, send.y, 16);
                r[k] = keep;
            }
            hi = (lane & 8);
            #pragma unroll
            for (int k = 0; k < 4; ++k) {
                float2 keep = hi ? r[k + 4] : r[k];
                float2 send = hi ? r[k] : r[k + 4];
                keep.x += __shfl_xor_sync(0xffffffffu, send.x, 8);
                keep.y += __shfl_xor_sync(0xffffffffu, send.y, 8);
                r[k] = keep;
            }
            hi = (lane & 4);
            #pragma unroll
            for (int k = 0; k < 2; ++k) {
                float2 keep = hi ? r[k + 2] : r[k];
                float2 send = hi ? r[k] : r[k + 2];
                keep.x += __shfl_xor_sync(0xffffffffu, send.x, 4);
                keep.y += __shfl_xor_sync(0xffffffffu, send.y, 4);
                r[k] = keep;
            }
            hi = (lane & 2);
            {
                float2 keep = hi ? r[1] : r[0];
                float2 send = hi ? r[0] : r[1];
                keep.x += __shfl_xor_sync(0xffffffffu, send.x, 2);
                keep.y += __shfl_xor_sync(0xffffffffu, send.y, 2);
                r[0] = keep;
            }
            {
                bool hb = (lane & 1);
                float keep = hb ? r[0].y : r[0].x;
                float send = hb ? r[0].x : r[0].y;
                float outv = keep + __shfl_xor_sync(0xffffffffu, send, 1);
                int d = sweep * 8 + odp * 2 + odb;
                g_attn[((size_t)b * 64 + h * 16 + d) * Tt + t0 + oi] = outv;
            }
        }
    }
}

// ---------------------------------------------------------------------------
// Kernel 3: head-mix projection + skip + BN + ReLU. 2 blocks per b (T split).
// 4o x 8t register tile; Wt filled by float4 copy from g_Wat.
// ---------------------------------------------------------------------------
__global__ void __launch_bounds__(256, 3) proj_kernel(
    const float* __restrict__ Ba,
    const float* __restrict__ bg, const float* __restrict__ bb,
    const float* __restrict__ bm, const float* __restrict__ bv,
    const float* __restrict__ x, float* __restrict__ out)
{
    int b = blockIdx.x;
    int half = blockIdx.y;
    int n = b / Vv, v = b - n * Vv;
    int T0 = half * 152;
    int TL = half ? 148 : 152;
    extern __shared__ float sm[];
    float* as = sm;            // 64*152
    float* Wt = as + 64 * 152; // 64*64
    float* s2 = Wt + 4096;     // 64
    float* b2 = s2 + 64;       // 64
    int tid = threadIdx.x;

    const float* ag = g_attn + (size_t)b * 64 * Tt;
    for (int i = tid; i < 64 * TL; i += 256) {
        int d = i / TL, tt = i - d * TL;
        as[d * 152 + tt] = ag[d * Tt + T0 + tt];
    }
    if (half) {
        for (int i = tid; i < 64 * 4; i += 256) {
            int d = i >> 2, tt = 148 + (i & 3);
            as[d * 152 + tt] = 0.f;
        }
    }
    for (int i = tid; i < 1024; i += 256)
        ((float4*)Wt)[i] = ((const float4*)g_Wat)[i];
    if (tid < 64) {
        float s = bg[tid] * rsqrtf(bv[tid] + 1e-5f);
        s2[tid] = s;
        b2[tid] = bb[tid] - bm[tid] * s;
    }
    __syncthreads();

    const float* xb = x + ((size_t)n * Cc) * Tt * Vv + v;
    float*       ob = out + ((size_t)n * Cc) * Tt * Vv + v;

    for (int task = tid; task < 304; task += 256) {
        int og = task & 15, tg = task >> 4;
        int o0 = og * 4, t0 = tg * 8;
        float acc[4][8];
        #pragma unroll
        for (int i = 0; i < 4; ++i)
            #pragma unroll
            for (int j = 0; j < 8; ++j) acc[i][j] = 0.f;

        #pragma unroll 8
        for (int d = 0; d < 64; ++d) {
            float4 w4 = *(const float4*)(Wt + d * 64 + o0);
            float4 aa = *(const float4*)(as + d * 152 + t0);
            float4 ac = *(const float4*)(as + d * 152 + t0 + 4);
            float wa[4] = {w4.x, w4.y, w4.z, w4.w};
            float A[8] = {aa.x, aa.y, aa.z, aa.w, ac.x, ac.y, ac.z, ac.w};
            #pragma unroll
            for (int i = 0; i < 4; ++i)
                #pragma unroll
                for (int j = 0; j < 8; ++j)
                    acc[i][j] += wa[i] * A[j];
        }
        int tmax = TL - t0;
        #pragma unroll
        for (int i = 0; i < 4; ++i) {
            int o = o0 + i;
            float bias = Ba[o];
            #pragma unroll
            for (int j = 0; j < 8; ++j) {
                if (j < tmax) {
                    int t = T0 + t0 + j;
                    size_t gi = (size_t)(o * Tt + t) * Vv;
                    float r = acc[i][j] + bias + xb[gi];
                    r = r * s2[o] + b2[o];
                    ob[gi] = fmaxf(r, 0.f);
                }
            }
        }
    }
}

// ---------------------------------------------------------------------------
extern "C" void kernel_launch(void* const* d_in, const int* in_sizes, int n_in,
                              void* d_out, int out_size)
{
    const float* x       = (const float*)d_in[0];
    const float* dbn_g   = (const float*)d_in[1];
    const float* dbn_b   = (const float*)d_in[2];
    const float* dbn_m   = (const float*)d_in[3];
    const float* dbn_v   = (const float*)d_in[4];
    const float* qkv_w   = (const float*)d_in[5];
    const float* qkv_b   = (const float*)d_in[6];
    const float* key_rel = (const float*)d_in[7];
    const float* attn_w  = (const float*)d_in[8];
    const float* attn_b  = (const float*)d_in[9];
    const float* bn_g    = (const float*)d_in[10];
    const float* bn_b    = (const float*)d_in[11];
    const float* bn_m    = (const float*)d_in[12];
    const float* bn_v    = (const float*)d_in[13];
    float* out = (float*)d_out;

    const int SM1 = (6400 + 12288 + 128) * 4;              // 75,264
    const int SM2 = (16 * KST + 16 * RST + 384 * 16) * 4;  // 82,176
    const int SM3 = (64 * 152 + 4096 + 128) * 4;           // 55,808

    cudaFuncSetAttribute(qkv_kernel,  cudaFuncAttributeMaxDynamicSharedMemorySize, SM1);
    cudaFuncSetAttribute(attn_kernel, cudaFuncAttributeMaxDynamicSharedMemorySize, SM2);
    cudaFuncSetAttribute(proj_kernel, cudaFuncAttributeMaxDynamicSharedMemorySize, SM3);

    prep_kernel<<<40, 256>>>(key_rel, qkv_w, attn_w);
    qkv_kernel<<<dim3(Bb, 3), 256, SM1>>>(x, dbn_g, dbn_b, dbn_m, dbn_v, qkv_b);
    attn_kernel<<<Bb * NHh, 256, SM2>>>();
    proj_kernel<<<dim3(Bb, 2), 256, SM3>>>(attn_b, bn_g, bn_b, bn_m, bn_v, x, out);
}

// round 13
// speedup vs baseline: 1.3277x; 1.0640x over previous
#include <cuda_runtime.h>
#include <cuda_bf16.h>
#include <math.h>

#define Nn 16
#define Cc 64
#define Tt 300
#define Vv 25
#define NHh 4
#define Bb (Nn*Vv)          // 400
#define QKVO 192            // 2*DK+DV
#define TJ (Tt*Vv)          // 7500

__device__ float g_qkv[(size_t)Bb * QKVO * Tt];
__device__ float g_attn[(size_t)Nn * 64 * TJ];   // [n][d][t*25+v]
__device__ float g_krt[16 * 600];   // key_rel transposed+padded, [d][m]
__device__ float g_Wt[64 * 192];    // qkv_w transposed, [c][o]
__device__ float g_Wat[64 * 64];    // attn_w transposed, [d][o]

// ---- packed fp32 helpers (FFMA2 / FMUL2 are PTX-only on sm_103a) ----
__device__ __forceinline__ float2 ffma2(float2 a, float2 b, float2 c) {
    unsigned long long A = *(unsigned long long*)&a;
    unsigned long long B = *(unsigned long long*)&b;
    unsigned long long C = *(unsigned long long*)&c;
    unsigned long long D;
    asm("fma.rn.f32x2 %0, %1, %2, %3;" : "=l"(D) : "l"(A), "l"(B), "l"(C));
    return *(float2*)&D;
}
__device__ __forceinline__ float2 fmul2(float2 a, float2 b) {
    unsigned long long A = *(unsigned long long*)&a;
    unsigned long long B = *(unsigned long long*)&b;
    unsigned long long D;
    asm("mul.rn.f32x2 %0, %1, %2;" : "=l"(D) : "l"(A), "l"(B));
    return *(float2*)&D;
}

// ---------------------------------------------------------------------------
// Kernel 0: one-time transposes (block-invariant data).
// ---------------------------------------------------------------------------
__global__ void prep_kernel(const float* __restrict__ key_rel,
                            const float* __restrict__ W,
                            const float* __restrict__ Wa)
{
    int tid = blockIdx.x * 256 + threadIdx.x;
    int stride = gridDim.x * 256;
    for (int i = tid; i < 16 * 600; i += stride) {
        int d = i / 600, m = i - d * 600;
        g_krt[i] = (m <= 598) ? key_rel[m * 16 + d] : 0.f;
    }
    for (int i = tid; i < 64 * 192; i += stride) {
        int c = i / 192, o = i - c * 192;
        g_Wt[i] = W[o * 64 + c];
    }
    for (int i = tid; i < 64 * 64; i += stride) {
        int d = i >> 6, o = i & 63;
        g_Wat[i] = Wa[o * 64 + d];
    }
}

// ---------------------------------------------------------------------------
// Kernel 1: fused data_bn (eval) + 1x1 qkv conv. 3 blocks per b (T split 100).
// (R12 version.)
// ---------------------------------------------------------------------------
__global__ void __launch_bounds__(256, 3) qkv_kernel(
    const float* __restrict__ x,
    const float* __restrict__ dg, const float* __restrict__ db,
    const float* __restrict__ dm, const float* __restrict__ dv,
    const float* __restrict__ Wb)
{
    int b = blockIdx.x;
    int T0 = blockIdx.y * 100;
    int n = b / Vv, v = b - n * Vv;
    extern __shared__ float sm[];
    float* xs = sm;             // 64*100
    float* Wt = xs + 6400;      // 12288  [c][o]
    float* sc = Wt + 12288;     // 64
    float* bi = sc + 64;        // 64
    int tid = threadIdx.x;

    if (tid < 64) {
        int idx = tid * Vv + v;
        float s = dg[idx] * rsqrtf(dv[idx] + 1e-5f);
        sc[tid] = s;
        bi[tid] = db[idx] - dm[idx] * s;
    }
    for (int i = tid; i < 3072; i += 256)
        ((float4*)Wt)[i] = ((const float4*)g_Wt)[i];
    __syncthreads();

    const float* xb = x + ((size_t)n * Cc) * Tt * Vv + v;
    for (int i = tid; i < 64 * 100; i += 256) {
        int c = i / 100, tt = i - c * 100;
        xs[i] = xb[(size_t)(c * Tt + T0 + tt) * Vv] * sc[c] + bi[c];
    }
    __syncthreads();

    for (int task = tid; task < 624; task += 256) {
        int og = task % 48, tg = task / 48;
        int o0 = og * 4, t0 = tg * 8;
        bool full = (tg < 12);
        float acc[4][8];
        #pragma unroll
        for (int i = 0; i < 4; ++i)
            #pragma unroll
            for (int j = 0; j < 8; ++j) acc[i][j] = 0.f;

        if (full) {
            #pragma unroll 8
            for (int c = 0; c < 64; ++c) {
                float4 w4 = *(const float4*)(Wt + c * 192 + o0);
                float4 xa = *(const float4*)(xs + c * 100 + t0);
                float4 xc = *(const float4*)(xs + c * 100 + t0 + 4);
                float wa[4] = {w4.x, w4.y, w4.z, w4.w};
                float A[8] = {xa.x, xa.y, xa.z, xa.w, xc.x, xc.y, xc.z, xc.w};
                #pragma unroll
                for (int i = 0; i < 4; ++i)
                    #pragma unroll
                    for (int j = 0; j < 8; ++j)
                        acc[i][j] += wa[i] * A[j];
            }
        } else {
            #pragma unroll 8
            for (int c = 0; c < 64; ++c) {
                float4 w4 = *(const float4*)(Wt + c * 192 + o0);
                float4 xa = *(const float4*)(xs + c * 100 + t0);
                float wa[4] = {w4.x, w4.y, w4.z, w4.w};
                float A[4] = {xa.x, xa.y, xa.z, xa.w};
                #pragma unroll
                for (int i = 0; i < 4; ++i)
                    #pragma unroll
                    for (int j = 0; j < 4; ++j)
                        acc[i][j] += wa[i] * A[j];
            }
        }

        float* outp = g_qkv + ((size_t)b * QKVO + o0) * Tt + T0 + t0;
        #pragma unroll
        for (int i = 0; i < 4; ++i) {
            float bias = Wb[o0 + i];
            float scale = (o0 + i < 64) ? 0.25f : 1.0f;  // q * DKH^-0.5
            float4 r;
            r.x = (acc[i][0] + bias) * scale;
            r.y = (acc[i][1] + bias) * scale;
            r.z = (acc[i][2] + bias) * scale;
            r.w = (acc[i][3] + bias) * scale;
            *(float4*)(outp + i * Tt) = r;
            if (full) {
                float4 r2;
                r2.x = (acc[i][4] + bias) * scale;
                r2.y = (acc[i][5] + bias) * scale;
                r2.z = (acc[i][6] + bias) * scale;
                r2.w = (acc[i][7] + bias) * scale;
                *(float4*)(outp + i * Tt + 4) = r2;
            }
        }
    }
}

// ---------------------------------------------------------------------------
// Kernel 2: attention per (b,h) — R12 core; output written to the new
// [n][d][t*25+v] layout (same scattered singles, re-pointed).
// ---------------------------------------------------------------------------
#define KST 300   // ks row stride
#define RST 600   // krs row stride

__global__ void __launch_bounds__(256, 2) attn_kernel()
{
    int bh = blockIdx.x;
    int b = bh >> 2, h = bh & 3;
    int nn = b / Vv, vv = b - nn * Vv;
    extern __shared__ float sm[];
    float* ks   = sm;                  // 16*300  [d][s]
    float* krs  = ks + 16 * KST;       // 16*600  [d][m]
    float* vt   = krs + 16 * RST;      // 384*16  [s][d] chunk-swizzled

    const float* base = g_qkv + (size_t)b * QKVO * Tt;
    const float* qg = base + (h * 16) * Tt;
    const float* kg = base + (64 + h * 16) * Tt;
    const float* vg = base + (128 + h * 16) * Tt;
    // output base: g_attn[(nn*64 + h*16 + d)*7500 + t*25 + vv]
    float* og_base = g_attn + ((size_t)nn * 64 + h * 16) * TJ + vv;

    int tid = threadIdx.x;
    for (int i = tid; i < 1200; i += 256)
        ((float4*)ks)[i] = ((const float4*)kg)[i];
    for (int i = tid; i < 2400; i += 256)
        ((float4*)krs)[i] = ((const float4*)g_krt)[i];
    for (int i = tid + 4800; i < 6144; i += 256)
        vt[i] = 0.f;
    for (int i = tid; i < 1200; i += 256) {
        int s = i >> 2, c = i & 3;
        int w = (s >> 2) & 3;
        float4 vvv;
        vvv.x = vg[(c * 4 + 0) * 300 + s];
        vvv.y = vg[(c * 4 + 1) * 300 + s];
        vvv.z = vg[(c * 4 + 2) * 300 + s];
        vvv.w = vg[(c * 4 + 3) * 300 + s];
        *(float4*)(vt + s * 16 + ((c ^ w) << 2)) = vvv;
    }
    __syncthreads();

    int warp = tid >> 5, lane = tid & 31;
    int lw = lane & 3;
    int oi = (((lane >> 4) & 1) << 1) | ((lane >> 3) & 1);
    int odp = (((lane >> 2) & 1) << 1) | ((lane >> 1) & 1);
    int odb = lane & 1;

    for (int g = warp; g < 75; g += 8) {
        int t0 = g * 4;
        float2 L[3][4][2];
        bool v2 = (lane < 11);
        #pragma unroll
        for (int p = 0; p < 3; ++p) {
            float init = (p < 2 || v2) ? 0.f : -1e30f;
            #pragma unroll
            for (int i = 0; i < 4; ++i) {
                L[p][i][0] = make_float2(init, init);
                L[p][i][1] = make_float2(init, init);
            }
        }

        #pragma unroll
        for (int d = 0; d < 16; ++d) {
            float4 q4 = __ldg((const float4*)(qg + d * 300 + t0));
            float2 qd[4] = { make_float2(q4.x, q4.x), make_float2(q4.y, q4.y),
                             make_float2(q4.z, q4.z), make_float2(q4.w, q4.w) };
            #pragma unroll
            for (int p = 0; p < 3; ++p) {
                if (p < 2 || v2) {
                    int s0 = p * 128 + lane * 4;
                    int m0 = s0 - t0 + 296;
                    float4 k4 = *(const float4*)(ks + d * KST + s0);
                    float4 ra = *(const float4*)(krs + d * RST + m0);
                    float4 rb = *(const float4*)(krs + d * RST + m0 + 4);
                    float2 k01 = make_float2(k4.x, k4.y), k23 = make_float2(k4.z, k4.w);
                    float2 r01 = make_float2(ra.x, ra.y), r23 = make_float2(ra.z, ra.w);
                    float2 r45 = make_float2(rb.x, rb.y);
                    float2 r12 = make_float2(ra.y, ra.z);
                    float2 r34 = make_float2(ra.w, rb.x);
                    float2 r56 = make_float2(rb.y, rb.z);
                    L[p][0][0] = ffma2(qd[0], k01, L[p][0][0]); L[p][0][1] = ffma2(qd[0], k23, L[p][0][1]);
                    L[p][1][0] = ffma2(qd[1], k01, L[p][1][0]); L[p][1][1] = ffma2(qd[1], k23, L[p][1][1]);
                    L[p][2][0] = ffma2(qd[2], k01, L[p][2][0]); L[p][2][1] = ffma2(qd[2], k23, L[p][2][1]);
                    L[p][3][0] = ffma2(qd[3], k01, L[p][3][0]); L[p][3][1] = ffma2(qd[3], k23, L[p][3][1]);
                    L[p][0][0] = ffma2(qd[0], r34, L[p][0][0]); L[p][0][1] = ffma2(qd[0], r56, L[p][0][1]);
                    L[p][1][0] = ffma2(qd[1], r23, L[p][1][0]); L[p][1][1] = ffma2(qd[1], r45, L[p][1][1]);
                    L[p][2][0] = ffma2(qd[2], r12, L[p][2][0]); L[p][2][1] = ffma2(qd[2], r34, L[p][2][1]);
                    L[p][3][0] = ffma2(qd[3], r01, L[p][3][0]); L[p][3][1] = ffma2(qd[3], r23, L[p][3][1]);
                }
            }
        }

        #pragma unroll
        for (int i = 0; i < 4; ++i) {
            float mx = -1e30f;
            #pragma unroll
            for (int p = 0; p < 3; ++p)
                #pragma unroll
                for (int jp = 0; jp < 2; ++jp)
                    mx = fmaxf(mx, fmaxf(L[p][i][jp].x, L[p][i][jp].y));
            #pragma unroll
            for (int o = 16; o > 0; o >>= 1)
                mx = fmaxf(mx, __shfl_xor_sync(0xffffffffu, mx, o));
            float s = 0.f;
            #pragma unroll
            for (int p = 0; p < 3; ++p)
                #pragma unroll
                for (int jp = 0; jp < 2; ++jp) {
                    float ex = __expf(L[p][i][jp].x - mx);
                    float ey = __expf(L[p][i][jp].y - mx);
                    L[p][i][jp] = make_float2(ex, ey);
                    s += ex + ey;
                }
            #pragma unroll
            for (int o = 16; o > 0; o >>= 1)
                s += __shfl_xor_sync(0xffffffffu, s, o);
            float inv = 1.f / s;
            float2 inv2 = make_float2(inv, inv);
            #pragma unroll
            for (int p = 0; p < 3; ++p)
                #pragma unroll
                for (int jp = 0; jp < 2; ++jp)
                    L[p][i][jp] = fmul2(L[p][i][jp], inv2);
        }

        #pragma unroll
        for (int sweep = 0; sweep < 2; ++sweep) {
            float2 r[16];
            #pragma unroll
            for (int k = 0; k < 16; ++k) r[k] = make_float2(0.f, 0.f);

            #pragma unroll
            for (int p = 0; p < 3; ++p) {
                int sbase = p * 128 + lane * 4;
                #pragma unroll
                for (int j = 0; j < 4; ++j) {
                    const float* vp = vt + (sbase + j) * 16;
                    float4 va = *(const float4*)(vp + (((sweep * 2)     ^ lw) << 2));
                    float4 vb = *(const float4*)(vp + (((sweep * 2 + 1) ^ lw) << 2));
                    float2 v01 = make_float2(va.x, va.y);
                    float2 v23 = make_float2(va.z, va.w);
                    float2 v45 = make_float2(vb.x, vb.y);
                    float2 v67 = make_float2(vb.z, vb.w);
                    #pragma unroll
                    for (int i = 0; i < 4; ++i) {
                        float pij = (j & 1) ? L[p][i][j >> 1].y : L[p][i][j >> 1].x;
                        float2 pp = make_float2(pij, pij);
                        r[i * 4 + 0] = ffma2(pp, v01, r[i * 4 + 0]);
                        r[i * 4 + 1] = ffma2(pp, v23, r[i * 4 + 1]);
                        r[i * 4 + 2] = ffma2(pp, v45, r[i * 4 + 2]);
                        r[i * 4 + 3] = ffma2(pp, v67, r[i * 4 + 3]);
                    }
                }
            }

            bool hi;
            hi = (lane & 16);
            #pragma unroll
            for (int k = 0; k < 8; ++k) {
                float2 keep = hi ? r[k + 8] : r[k];
                float2 send = hi ? r[k] : r[k + 8];
                keep.x += __shfl_xor_sync(0xffffffffu, send.x, 16);
                keep.y += __shfl_xor_sync(0xffffffffu, send.y, 16);
                r[k] = keep;
            }
            hi = (lane & 8);
            #pragma unroll
            for (int k = 0; k < 4; ++k) {
                float2 keep = hi ? r[k + 4] : r[k];
                float2 send = hi ? r[k] : r[k + 4];
                keep.x += __shfl_xor_sync(0xffffffffu, send.x, 8);
                keep.y += __shfl_xor_sync(0xffffffffu, send.y, 8);
                r[k] = keep;
            }
            hi = (lane & 4);
            #pragma unroll
            for (int k = 0; k < 2; ++k) {
                float2 keep = hi ? r[k + 2] : r[k];
                float2 send = hi ? r[k] : r[k + 2];
                keep.x += __shfl_xor_sync(0xffffffffu, send.x, 4);
                keep.y += __shfl_xor_sync(0xffffffffu, send.y, 4);
                r[0 + k] = keep;
            }
            hi = (lane & 2);
            {
                float2 keep = hi ? r[1] : r[0];
                float2 send = hi ? r[0] : r[1];
                keep.x += __shfl_xor_sync(0xffffffffu, send.x, 2);
                keep.y += __shfl_xor_sync(0xffffffffu, send.y, 2);
                r[0] = keep;
            }
            {
                bool hb = (lane & 1);
                float keep = hb ? r[0].y : r[0].x;
                float send = hb ? r[0].x : r[0].y;
                float outv = keep + __shfl_xor_sync(0xffffffffu, send, 1);
                int d = sweep * 8 + odp * 2 + odb;
                og_base[(size_t)d * TJ + (t0 + oi) * 25] = outv;
            }
        }
    }
}

// ---------------------------------------------------------------------------
// Kernel 3: proj v2 — dense GEMM over j = t*25+v. Grid (n, 25 j-tiles of 300).
// as-fill, skip-load, store all float4-coalesced.
// ---------------------------------------------------------------------------
__global__ void __launch_bounds__(256, 2) proj_kernel(
    const float* __restrict__ Ba,
    const float* __restrict__ bg, const float* __restrict__ bb,
    const float* __restrict__ bm, const float* __restrict__ bv,
    const float* __restrict__ x, float* __restrict__ out)
{
    int n = blockIdx.x;
    int jt = blockIdx.y;
    int j0 = jt * 300;
    extern __shared__ float sm[];
    float* as = sm;            // 64*304  [d][jj]
    float* Wt = as + 64 * 304; // 64*64   [d][o]
    float* s2 = Wt + 4096;     // 64
    float* b2 = s2 + 64;       // 64
    int tid = threadIdx.x;

    // as fill: 75 float4 per d row, fully coalesced
    for (int i = tid; i < 4800; i += 256) {
        int d = i / 75, r = i - d * 75;
        ((float4*)(as + d * 304))[r] =
            ((const float4*)(g_attn + (size_t)(n * 64 + d) * TJ + j0))[r];
    }
    // zero pad columns 300..303
    for (int i = tid; i < 256; i += 256) {
        int d = i >> 2;
        as[d * 304 + 300 + (i & 3)] = 0.f;
    }
    for (int i = tid; i < 1024; i += 256)
        ((float4*)Wt)[i] = ((const float4*)g_Wat)[i];
    if (tid < 64) {
        float s = bg[tid] * rsqrtf(bv[tid] + 1e-5f);
        s2[tid] = s;
        b2[tid] = bb[tid] - bm[tid] * s;
    }
    __syncthreads();

    const float* xb = x + (size_t)n * 64 * TJ + j0;
    float*       ob = out + (size_t)n * 64 * TJ + j0;

    // 608 tasks: og = task % 16, jg = task / 16 (0..37); jj0 = jg*8
    for (int task = tid; task < 608; task += 256) {
        int og = task & 15, jg = task >> 4;
        int o0 = og * 4, jj0 = jg * 8;
        bool full = (jg < 37);      // jg==37: jj 296..299 valid only
        float acc[4][8];
        #pragma unroll
        for (int i = 0; i < 4; ++i)
            #pragma unroll
            for (int j = 0; j < 8; ++j) acc[i][j] = 0.f;

        #pragma unroll 8
        for (int d = 0; d < 64; ++d) {
            float4 w4 = *(const float4*)(Wt + d * 64 + o0);
            float4 aa = *(const float4*)(as + d * 304 + jj0);
            float4 ac = *(const float4*)(as + d * 304 + jj0 + 4);
            float wa[4] = {w4.x, w4.y, w4.z, w4.w};
            float A[8] = {aa.x, aa.y, aa.z, aa.w, ac.x, ac.y, ac.z, ac.w};
            #pragma unroll
            for (int i = 0; i < 4; ++i)
                #pragma unroll
                for (int j = 0; j < 8; ++j)
                    acc[i][j] += wa[i] * A[j];
        }
        #pragma unroll
        for (int i = 0; i < 4; ++i) {
            int o = o0 + i;
            float bias = Ba[o];
            float ss = s2[o], bb2 = b2[o];
            const float* xo = xb + (size_t)o * TJ + jj0;
            float*       oo = ob + (size_t)o * TJ + jj0;
            float4 xv = *(const float4*)(xo);
            float4 r;
            r.x = fmaxf((acc[i][0] + bias + xv.x) * ss + bb2, 0.f);
            r.y = fmaxf((acc[i][1] + bias + xv.y) * ss + bb2, 0.f);
            r.z = fmaxf((acc[i][2] + bias + xv.z) * ss + bb2, 0.f);
            r.w = fmaxf((acc[i][3] + bias + xv.w) * ss + bb2, 0.f);
            *(float4*)(oo) = r;
            if (full) {
                float4 xw = *(const float4*)(xo + 4);
                float4 r2;
                r2.x = fmaxf((acc[i][4] + bias + xw.x) * ss + bb2, 0.f);
                r2.y = fmaxf((acc[i][5] + bias + xw.y) * ss + bb2, 0.f);
                r2.z = fmaxf((acc[i][6] + bias + xw.z) * ss + bb2, 0.f);
                r2.w = fmaxf((acc[i][7] + bias + xw.w) * ss + bb2, 0.f);
                *(float4*)(oo + 4) = r2;
            }
        }
    }
}

// ---------------------------------------------------------------------------
extern "C" void kernel_launch(void* const* d_in, const int* in_sizes, int n_in,
                              void* d_out, int out_size)
{
    const float* x       = (const float*)d_in[0];
    const float* dbn_g   = (const float*)d_in[1];
    const float* dbn_b   = (const float*)d_in[2];
    const float* dbn_m   = (const float*)d_in[3];
    const float* dbn_v   = (const float*)d_in[4];
    const float* qkv_w   = (const float*)d_in[5];
    const float* qkv_b   = (const float*)d_in[6];
    const float* key_rel = (const float*)d_in[7];
    const float* attn_w  = (const float*)d_in[8];
    const float* attn_b  = (const float*)d_in[9];
    const float* bn_g    = (const float*)d_in[10];
    const float* bn_b    = (const float*)d_in[11];
    const float* bn_m    = (const float*)d_in[12];
    const float* bn_v    = (const float*)d_in[13];
    float* out = (float*)d_out;

    const int SM1 = (6400 + 12288 + 128) * 4;              // 75,264
    const int SM2 = (16 * KST + 16 * RST + 384 * 16) * 4;  // 82,176
    const int SM3 = (64 * 304 + 4096 + 128) * 4;           // 94,720

    cudaFuncSetAttribute(qkv_kernel,  cudaFuncAttributeMaxDynamicSharedMemorySize, SM1);
    cudaFuncSetAttribute(attn_kernel, cudaFuncAttributeMaxDynamicSharedMemorySize, SM2);
    cudaFuncSetAttribute(proj_kernel, cudaFuncAttributeMaxDynamicSharedMemorySize, SM3);

    prep_kernel<<<40, 256>>>(key_rel, qkv_w, attn_w);
    qkv_kernel<<<dim3(Bb, 3), 256, SM1>>>(x, dbn_g, dbn_b, dbn_m, dbn_v, qkv_b);
    attn_kernel<<<Bb * NHh, 256, SM2>>>();
    proj_kernel<<<dim3(Nn, 25), 256, SM3>>>(attn_b, bn_g, bn_b, bn_m, bn_v, x, out);
}

// round 14
// speedup vs baseline: 1.3296x; 1.0014x over previous
#include <cuda_runtime.h>
#include <cuda_bf16.h>
#include <math.h>

#define Nn 16
#define Cc 64
#define Tt 300
#define Vv 25
#define NHh 4
#define Bb (Nn*Vv)          // 400
#define QKVO 192            // 2*DK+DV
#define TJ (Tt*Vv)          // 7500
#define ATH 320             // attn threads per block (10 warps)

__device__ float g_qkv[(size_t)Bb * QKVO * Tt];
__device__ float g_attn[(size_t)Nn * 64 * TJ];   // [n][d][t*25+v]
__device__ float g_krt[16 * 600];   // key_rel transposed+padded, [d][m]
__device__ float g_Wt[64 * 192];    // qkv_w transposed, [c][o]
__device__ float g_Wat[64 * 64];    // attn_w transposed, [d][o]

// ---- packed fp32 helpers (FFMA2 / FMUL2 are PTX-only on sm_103a) ----
__device__ __forceinline__ float2 ffma2(float2 a, float2 b, float2 c) {
    unsigned long long A = *(unsigned long long*)&a;
    unsigned long long B = *(unsigned long long*)&b;
    unsigned long long C = *(unsigned long long*)&c;
    unsigned long long D;
    asm("fma.rn.f32x2 %0, %1, %2, %3;" : "=l"(D) : "l"(A), "l"(B), "l"(C));
    return *(float2*)&D;
}
__device__ __forceinline__ float2 fmul2(float2 a, float2 b) {
    unsigned long long A = *(unsigned long long*)&a;
    unsigned long long B = *(unsigned long long*)&b;
    unsigned long long D;
    asm("mul.rn.f32x2 %0, %1, %2;" : "=l"(D) : "l"(A), "l"(B));
    return *(float2*)&D;
}

// ---------------------------------------------------------------------------
// Kernel 0: one-time transposes (block-invariant data).
// ---------------------------------------------------------------------------
__global__ void prep_kernel(const float* __restrict__ key_rel,
                            const float* __restrict__ W,
                            const float* __restrict__ Wa)
{
    int tid = blockIdx.x * 256 + threadIdx.x;
    int stride = gridDim.x * 256;
    for (int i = tid; i < 16 * 600; i += stride) {
        int d = i / 600, m = i - d * 600;
        g_krt[i] = (m <= 598) ? key_rel[m * 16 + d] : 0.f;
    }
    for (int i = tid; i < 64 * 192; i += stride) {
        int c = i / 192, o = i - c * 192;
        g_Wt[i] = W[o * 64 + c];
    }
    for (int i = tid; i < 64 * 64; i += stride) {
        int d = i >> 6, o = i & 63;
        g_Wat[i] = Wa[o * 64 + d];
    }
}

// ---------------------------------------------------------------------------
// Kernel 1: fused data_bn (eval) + 1x1 qkv conv. 3 blocks per b (T split 100).
// ---------------------------------------------------------------------------
__global__ void __launch_bounds__(256, 3) qkv_kernel(
    const float* __restrict__ x,
    const float* __restrict__ dg, const float* __restrict__ db,
    const float* __restrict__ dm, const float* __restrict__ dv,
    const float* __restrict__ Wb)
{
    int b = blockIdx.x;
    int T0 = blockIdx.y * 100;
    int n = b / Vv, v = b - n * Vv;
    extern __shared__ float sm[];
    float* xs = sm;             // 64*100
    float* Wt = xs + 6400;      // 12288  [c][o]
    float* sc = Wt + 12288;     // 64
    float* bi = sc + 64;        // 64
    int tid = threadIdx.x;

    if (tid < 64) {
        int idx = tid * Vv + v;
        float s = dg[idx] * rsqrtf(dv[idx] + 1e-5f);
        sc[tid] = s;
        bi[tid] = db[idx] - dm[idx] * s;
    }
    for (int i = tid; i < 3072; i += 256)
        ((float4*)Wt)[i] = ((const float4*)g_Wt)[i];
    __syncthreads();

    const float* xb = x + ((size_t)n * Cc) * Tt * Vv + v;
    for (int i = tid; i < 64 * 100; i += 256) {
        int c = i / 100, tt = i - c * 100;
        xs[i] = xb[(size_t)(c * Tt + T0 + tt) * Vv] * sc[c] + bi[c];
    }
    __syncthreads();

    for (int task = tid; task < 624; task += 256) {
        int og = task % 48, tg = task / 48;
        int o0 = og * 4, t0 = tg * 8;
        bool full = (tg < 12);
        float acc[4][8];
        #pragma unroll
        for (int i = 0; i < 4; ++i)
            #pragma unroll
            for (int j = 0; j < 8; ++j) acc[i][j] = 0.f;

        if (full) {
            #pragma unroll 8
            for (int c = 0; c < 64; ++c) {
                float4 w4 = *(const float4*)(Wt + c * 192 + o0);
                float4 xa = *(const float4*)(xs + c * 100 + t0);
                float4 xc = *(const float4*)(xs + c * 100 + t0 + 4);
                float wa[4] = {w4.x, w4.y, w4.z, w4.w};
                float A[8] = {xa.x, xa.y, xa.z, xa.w, xc.x, xc.y, xc.z, xc.w};
                #pragma unroll
                for (int i = 0; i < 4; ++i)
                    #pragma unroll
                    for (int j = 0; j < 8; ++j)
                        acc[i][j] += wa[i] * A[j];
            }
        } else {
            #pragma unroll 8
            for (int c = 0; c < 64; ++c) {
                float4 w4 = *(const float4*)(Wt + c * 192 + o0);
                float4 xa = *(const float4*)(xs + c * 100 + t0);
                float wa[4] = {w4.x, w4.y, w4.z, w4.w};
                float A[4] = {xa.x, xa.y, xa.z, xa.w};
                #pragma unroll
                for (int i = 0; i < 4; ++i)
                    #pragma unroll
                    for (int j = 0; j < 4; ++j)
                        acc[i][j] += wa[i] * A[j];
            }
        }

        float* outp = g_qkv + ((size_t)b * QKVO + o0) * Tt + T0 + t0;
        #pragma unroll
        for (int i = 0; i < 4; ++i) {
            float bias = Wb[o0 + i];
            float scale = (o0 + i < 64) ? 0.25f : 1.0f;  // q * DKH^-0.5
            float4 r;
            r.x = (acc[i][0] + bias) * scale;
            r.y = (acc[i][1] + bias) * scale;
            r.z = (acc[i][2] + bias) * scale;
            r.w = (acc[i][3] + bias) * scale;
            *(float4*)(outp + i * Tt) = r;
            if (full) {
                float4 r2;
                r2.x = (acc[i][4] + bias) * scale;
                r2.y = (acc[i][5] + bias) * scale;
                r2.z = (acc[i][6] + bias) * scale;
                r2.w = (acc[i][7] + bias) * scale;
                *(float4*)(outp + i * Tt + 4) = r2;
            }
        }
    }
}

// ---------------------------------------------------------------------------
// Kernel 2: attention per (b,h). 320 threads (10 warps) x 2 CTA = 20 warps/SM
// (reg cap 102 > natural usage -> no spills). Core identical to R13.
// ---------------------------------------------------------------------------
#define KST 300   // ks row stride
#define RST 600   // krs row stride

__global__ void __launch_bounds__(ATH, 2) attn_kernel()
{
    int bh = blockIdx.x;
    int b = bh >> 2, h = bh & 3;
    int nn = b / Vv, vv = b - nn * Vv;
    extern __shared__ float sm[];
    float* ks   = sm;                  // 16*300  [d][s]
    float* krs  = ks + 16 * KST;       // 16*600  [d][m]
    float* vt   = krs + 16 * RST;      // 384*16  [s][d] chunk-swizzled

    const float* base = g_qkv + (size_t)b * QKVO * Tt;
    const float* qg = base + (h * 16) * Tt;
    const float* kg = base + (64 + h * 16) * Tt;
    const float* vg = base + (128 + h * 16) * Tt;
    float* og_base = g_attn + ((size_t)nn * 64 + h * 16) * TJ + vv;

    int tid = threadIdx.x;
    for (int i = tid; i < 1200; i += ATH)
        ((float4*)ks)[i] = ((const float4*)kg)[i];
    for (int i = tid; i < 2400; i += ATH)
        ((float4*)krs)[i] = ((const float4*)g_krt)[i];
    for (int i = tid + 4800; i < 6144; i += ATH)
        vt[i] = 0.f;
    for (int i = tid; i < 1200; i += ATH) {
        int s = i >> 2, c = i & 3;
        int w = (s >> 2) & 3;
        float4 vvv;
        vvv.x = vg[(c * 4 + 0) * 300 + s];
        vvv.y = vg[(c * 4 + 1) * 300 + s];
        vvv.z = vg[(c * 4 + 2) * 300 + s];
        vvv.w = vg[(c * 4 + 3) * 300 + s];
        *(float4*)(vt + s * 16 + ((c ^ w) << 2)) = vvv;
    }
    __syncthreads();

    int warp = tid >> 5, lane = tid & 31;
    int lw = lane & 3;
    int oi = (((lane >> 4) & 1) << 1) | ((lane >> 3) & 1);
    int odp = (((lane >> 2) & 1) << 1) | ((lane >> 1) & 1);
    int odb = lane & 1;

    for (int g = warp; g < 75; g += 10) {
        int t0 = g * 4;
        float2 L[3][4][2];
        bool v2 = (lane < 11);
        #pragma unroll
        for (int p = 0; p < 3; ++p) {
            float init = (p < 2 || v2) ? 0.f : -1e30f;
            #pragma unroll
            for (int i = 0; i < 4; ++i) {
                L[p][i][0] = make_float2(init, init);
                L[p][i][1] = make_float2(init, init);
            }
        }

        #pragma unroll
        for (int d = 0; d < 16; ++d) {
            float4 q4 = __ldg((const float4*)(qg + d * 300 + t0));
            float2 qd[4] = { make_float2(q4.x, q4.x), make_float2(q4.y, q4.y),
                             make_float2(q4.z, q4.z), make_float2(q4.w, q4.w) };
            #pragma unroll
            for (int p = 0; p < 3; ++p) {
                if (p < 2 || v2) {
                    int s0 = p * 128 + lane * 4;
                    int m0 = s0 - t0 + 296;
                    float4 k4 = *(const float4*)(ks + d * KST + s0);
                    float4 ra = *(const float4*)(krs + d * RST + m0);
                    float4 rb = *(const float4*)(krs + d * RST + m0 + 4);
                    float2 k01 = make_float2(k4.x, k4.y), k23 = make_float2(k4.z, k4.w);
                    float2 r01 = make_float2(ra.x, ra.y), r23 = make_float2(ra.z, ra.w);
                    float2 r45 = make_float2(rb.x, rb.y);
                    float2 r12 = make_float2(ra.y, ra.z);
                    float2 r34 = make_float2(ra.w, rb.x);
                    float2 r56 = make_float2(rb.y, rb.z);
                    L[p][0][0] = ffma2(qd[0], k01, L[p][0][0]); L[p][0][1] = ffma2(qd[0], k23, L[p][0][1]);
                    L[p][1][0] = ffma2(qd[1], k01, L[p][1][0]); L[p][1][1] = ffma2(qd[1], k23, L[p][1][1]);
                    L[p][2][0] = ffma2(qd[2], k01, L[p][2][0]); L[p][2][1] = ffma2(qd[2], k23, L[p][2][1]);
                    L[p][3][0] = ffma2(qd[3], k01, L[p][3][0]); L[p][3][1] = ffma2(qd[3], k23, L[p][3][1]);
                    L[p][0][0] = ffma2(qd[0], r34, L[p][0][0]); L[p][0][1] = ffma2(qd[0], r56, L[p][0][1]);
                    L[p][1][0] = ffma2(qd[1], r23, L[p][1][0]); L[p][1][1] = ffma2(qd[1], r45, L[p][1][1]);
                    L[p][2][0] = ffma2(qd[2], r12, L[p][2][0]); L[p][2][1] = ffma2(qd[2], r34, L[p][2][1]);
                    L[p][3][0] = ffma2(qd[3], r01, L[p][3][0]); L[p][3][1] = ffma2(qd[3], r23, L[p][3][1]);
                }
            }
        }

        #pragma unroll
        for (int i = 0; i < 4; ++i) {
            float mx = -1e30f;
            #pragma unroll
            for (int p = 0; p < 3; ++p)
                #pragma unroll
                for (int jp = 0; jp < 2; ++jp)
                    mx = fmaxf(mx, fmaxf(L[p][i][jp].x, L[p][i][jp].y));
            #pragma unroll
            for (int o = 16; o > 0; o >>= 1)
                mx = fmaxf(mx, __shfl_xor_sync(0xffffffffu, mx, o));
            float s = 0.f;
            #pragma unroll
            for (int p = 0; p < 3; ++p)
                #pragma unroll
                for (int jp = 0; jp < 2; ++jp) {
                    float ex = __expf(L[p][i][jp].x - mx);
                    float ey = __expf(L[p][i][jp].y - mx);
                    L[p][i][jp] = make_float2(ex, ey);
                    s += ex + ey;
                }
            #pragma unroll
            for (int o = 16; o > 0; o >>= 1)
                s += __shfl_xor_sync(0xffffffffu, s, o);
            float inv = 1.f / s;
            float2 inv2 = make_float2(inv, inv);
            #pragma unroll
            for (int p = 0; p < 3; ++p)
                #pragma unroll
                for (int jp = 0; jp < 2; ++jp)
                    L[p][i][jp] = fmul2(L[p][i][jp], inv2);
        }

        #pragma unroll
        for (int sweep = 0; sweep < 2; ++sweep) {
            float2 r[16];
            #pragma unroll
            for (int k = 0; k < 16; ++k) r[k] = make_float2(0.f, 0.f);

            #pragma unroll
            for (int p = 0; p < 3; ++p) {
                int sbase = p * 128 + lane * 4;
                #pragma unroll
                for (int j = 0; j < 4; ++j) {
                    const float* vp = vt + (sbase + j) * 16;
                    float4 va = *(const float4*)(vp + (((sweep * 2)     ^ lw) << 2));
                    float4 vb = *(const float4*)(vp + (((sweep * 2 + 1) ^ lw) << 2));
                    float2 v01 = make_float2(va.x, va.y);
                    float2 v23 = make_float2(va.z, va.w);
                    float2 v45 = make_float2(vb.x, vb.y);
                    float2 v67 = make_float2(vb.z, vb.w);
                    #pragma unroll
                    for (int i = 0; i < 4; ++i) {
                        float pij = (j & 1) ? L[p][i][j >> 1].y : L[p][i][j >> 1].x;
                        float2 pp = make_float2(pij, pij);
                        r[i * 4 + 0] = ffma2(pp, v01, r[i * 4 + 0]);
                        r[i * 4 + 1] = ffma2(pp, v23, r[i * 4 + 1]);
                        r[i * 4 + 2] = ffma2(pp, v45, r[i * 4 + 2]);
                        r[i * 4 + 3] = ffma2(pp, v67, r[i * 4 + 3]);
                    }
                }
            }

            bool hi;
            hi = (lane & 16);
            #pragma unroll
            for (int k = 0; k < 8; ++k) {
                float2 keep = hi ? r[k + 8] : r[k];
                float2 send = hi ? r[k] : r[k + 8];
                keep.x += __shfl_xor_sync(0xffffffffu, send.x, 16);
                keep.y += __shfl_xor_sync(0xffffffffu, send.y, 16);
                r[k] = keep;
            }
            hi = (lane & 8);
            #pragma unroll
            for (int k = 0; k < 4; ++k) {
                float2 keep = hi ? r[k + 4] : r[k];
                float2 send = hi ? r[k] : r[k + 4];
                keep.x += __shfl_xor_sync(0xffffffffu, send.x, 8);
                keep.y += __shfl_xor_sync(0xffffffffu, send.y, 8);
                r[k] = keep;
            }
            hi = (lane & 4);
            #pragma unroll
            for (int k = 0; k < 2; ++k) {
                float2 keep = hi ? r[k + 2] : r[k];
                float2 send = hi ? r[k] : r[k + 2];
                keep.x += __shfl_xor_sync(0xffffffffu, send.x, 4);
                keep.y += __shfl_xor_sync(0xffffffffu, send.y, 4);
                r[k] = keep;
            }
            hi = (lane & 2);
            {
                float2 keep = hi ? r[1] : r[0];
                float2 send = hi ? r[0] : r[1];
                keep.x += __shfl_xor_sync(0xffffffffu, send.x, 2);
                keep.y += __shfl_xor_sync(0xffffffffu, send.y, 2);
                r[0] = keep;
            }
            {
                bool hb = (lane & 1);
                float keep = hb ? r[0].y : r[0].x;
                float send = hb ? r[0].x : r[0].y;
                float outv = keep + __shfl_xor_sync(0xffffffffu, send, 1);
                int d = sweep * 8 + odp * 2 + odb;
                og_base[(size_t)d * TJ + (t0 + oi) * 25] = outv;
            }
        }
    }
}

// ---------------------------------------------------------------------------
// Kernel 3: proj v2 — dense GEMM over j = t*25+v (R13 version).
// ---------------------------------------------------------------------------
__global__ void __launch_bounds__(256, 2) proj_kernel(
    const float* __restrict__ Ba,
    const float* __restrict__ bg, const float* __restrict__ bb,
    const float* __restrict__ bm, const float* __restrict__ bv,
    const float* __restrict__ x, float* __restrict__ out)
{
    int n = blockIdx.x;
    int jt = blockIdx.y;
    int j0 = jt * 300;
    extern __shared__ float sm[];
    float* as = sm;            // 64*304  [d][jj]
    float* Wt = as + 64 * 304; // 64*64   [d][o]
    float* s2 = Wt + 4096;     // 64
    float* b2 = s2 + 64;       // 64
    int tid = threadIdx.x;

    for (int i = tid; i < 4800; i += 256) {
        int d = i / 75, r = i - d * 75;
        ((float4*)(as + d * 304))[r] =
            ((const float4*)(g_attn + (size_t)(n * 64 + d) * TJ + j0))[r];
    }
    for (int i = tid; i < 256; i += 256) {
        int d = i >> 2;
        as[d * 304 + 300 + (i & 3)] = 0.f;
    }
    for (int i = tid; i < 1024; i += 256)
        ((float4*)Wt)[i] = ((const float4*)g_Wat)[i];
    if (tid < 64) {
        float s = bg[tid] * rsqrtf(bv[tid] + 1e-5f);
        s2[tid] = s;
        b2[tid] = bb[tid] - bm[tid] * s;
    }
    __syncthreads();

    const float* xb = x + (size_t)n * 64 * TJ + j0;
    float*       ob = out + (size_t)n * 64 * TJ + j0;

    for (int task = tid; task < 608; task += 256) {
        int og = task & 15, jg = task >> 4;
        int o0 = og * 4, jj0 = jg * 8;
        bool full = (jg < 37);
        float acc[4][8];
        #pragma unroll
        for (int i = 0; i < 4; ++i)
            #pragma unroll
            for (int j = 0; j < 8; ++j) acc[i][j] = 0.f;

        #pragma unroll 8
        for (int d = 0; d < 64; ++d) {
            float4 w4 = *(const float4*)(Wt + d * 64 + o0);
            float4 aa = *(const float4*)(as + d * 304 + jj0);
            float4 ac = *(const float4*)(as + d * 304 + jj0 + 4);
            float wa[4] = {w4.x, w4.y, w4.z, w4.w};
            float A[8] = {aa.x, aa.y, aa.z, aa.w, ac.x, ac.y, ac.z, ac.w};
            #pragma unroll
            for (int i = 0; i < 4; ++i)
                #pragma unroll
                for (int j = 0; j < 8; ++j)
                    acc[i][j] += wa[i] * A[j];
        }
        #pragma unroll
        for (int i = 0; i < 4; ++i) {
            int o = o0 + i;
            float bias = Ba[o];
            float ss = s2[o], bb2 = b2[o];
            const float* xo = xb + (size_t)o * TJ + jj0;
            float*       oo = ob + (size_t)o * TJ + jj0;
            float4 xv = *(const float4*)(xo);
            float4 r;
            r.x = fmaxf((acc[i][0] + bias + xv.x) * ss + bb2, 0.f);
            r.y = fmaxf((acc[i][1] + bias + xv.y) * ss + bb2, 0.f);
            r.z = fmaxf((acc[i][2] + bias + xv.z) * ss + bb2, 0.f);
            r.w = fmaxf((acc[i][3] + bias + xv.w) * ss + bb2, 0.f);
            *(float4*)(oo) = r;
            if (full) {
                float4 xw = *(const float4*)(xo + 4);
                float4 r2;
                r2.x = fmaxf((acc[i][4] + bias + xw.x) * ss + bb2, 0.f);
                r2.y = fmaxf((acc[i][5] + bias + xw.y) * ss + bb2, 0.f);
                r2.z = fmaxf((acc[i][6] + bias + xw.z) * ss + bb2, 0.f);
                r2.w = fmaxf((acc[i][7] + bias + xw.w) * ss + bb2, 0.f);
                *(float4*)(oo + 4) = r2;
            }
        }
    }
}

// ---------------------------------------------------------------------------
extern "C" void kernel_launch(void* const* d_in, const int* in_sizes, int n_in,
                              void* d_out, int out_size)
{
    const float* x       = (const float*)d_in[0];
    const float* dbn_g   = (const float*)d_in[1];
    const float* dbn_b   = (const float*)d_in[2];
    const float* dbn_m   = (const float*)d_in[3];
    const float* dbn_v   = (const float*)d_in[4];
    const float* qkv_w   = (const float*)d_in[5];
    const float* qkv_b   = (const float*)d_in[6];
    const float* key_rel = (const float*)d_in[7];
    const float* attn_w  = (const float*)d_in[8];
    const float* attn_b  = (const float*)d_in[9];
    const float* bn_g    = (const float*)d_in[10];
    const float* bn_b    = (const float*)d_in[11];
    const float* bn_m    = (const float*)d_in[12];
    const float* bn_v    = (const float*)d_in[13];
    float* out = (float*)d_out;

    const int SM1 = (6400 + 12288 + 128) * 4;              // 75,264
    const int SM2 = (16 * KST + 16 * RST + 384 * 16) * 4;  // 82,176
    const int SM3 = (64 * 304 + 4096 + 128) * 4;           // 94,720

    cudaFuncSetAttribute(qkv_kernel,  cudaFuncAttributeMaxDynamicSharedMemorySize, SM1);
    cudaFuncSetAttribute(attn_kernel, cudaFuncAttributeMaxDynamicSharedMemorySize, SM2);
    cudaFuncSetAttribute(proj_kernel, cudaFuncAttributeMaxDynamicSharedMemorySize, SM3);

    prep_kernel<<<40, 256>>>(key_rel, qkv_w, attn_w);
    qkv_kernel<<<dim3(Bb, 3), 256, SM1>>>(x, dbn_g, dbn_b, dbn_m, dbn_v, qkv_b);
    attn_kernel<<<Bb * NHh, ATH, SM2>>>();
    proj_kernel<<<dim3(Nn, 25), 256, SM3>>>(attn_b, bn_g, bn_b, bn_m, bn_v, x, out);
}

// round 15
// speedup vs baseline: 1.3639x; 1.0258x over previous
#include <cuda_runtime.h>
#include <cuda_bf16.h>
#include <math.h>

#define Nn 16
#define Cc 64
#define Tt 300
#define Vv 25
#define NHh 4
#define Bb (Nn*Vv)          // 400
#define QKVO 192            // 2*DK+DV
#define TJ (Tt*Vv)          // 7500
#define ATH 320             // attn threads per block (10 warps)

__device__ float g_qkv[(size_t)Bb * QKVO * Tt];
__device__ float g_attn[(size_t)Nn * 64 * TJ];   // [n][d][t*25+v]
__device__ float g_xbn[(size_t)Bb * 64 * Tt];    // dbn-normalized x, [b][c][t]
__device__ float g_krt[16 * 600];   // key_rel transposed+padded, [d][m]
__device__ float g_Wt[64 * 192];    // qkv_w transposed, [c][o]
__device__ float g_Wat[64 * 64];    // attn_w transposed, [d][o]

// ---- packed fp32 helpers (FFMA2 / FMUL2 are PTX-only on sm_103a) ----
__device__ __forceinline__ float2 ffma2(float2 a, float2 b, float2 c) {
    unsigned long long A = *(unsigned long long*)&a;
    unsigned long long B = *(unsigned long long*)&b;
    unsigned long long C = *(unsigned long long*)&c;
    unsigned long long D;
    asm("fma.rn.f32x2 %0, %1, %2, %3;" : "=l"(D) : "l"(A), "l"(B), "l"(C));
    return *(float2*)&D;
}
__device__ __forceinline__ float2 fmul2(float2 a, float2 b) {
    unsigned long long A = *(unsigned long long*)&a;
    unsigned long long B = *(unsigned long long*)&b;
    unsigned long long D;
    asm("mul.rn.f32x2 %0, %1, %2;" : "=l"(D) : "l"(A), "l"(B));
    return *(float2*)&D;
}

// ---------------------------------------------------------------------------
// Kernel 0: setup. Blocks 0..1023: dbn + transpose x -> g_xbn (coalesced both
// sides via smem tile). Blocks 1024+: one-time weight/key_rel transposes.
// ---------------------------------------------------------------------------
__global__ void setup_kernel(const float* __restrict__ x,
                             const float* __restrict__ dg, const float* __restrict__ db,
                             const float* __restrict__ dm, const float* __restrict__ dv,
                             const float* __restrict__ key_rel,
                             const float* __restrict__ W,
                             const float* __restrict__ Wa)
{
    int tid = threadIdx.x;
    if (blockIdx.x < 1024) {
        int n = blockIdx.x >> 6, c = blockIdx.x & 63;
        __shared__ float xsm[25 * 304];
        __shared__ float sc[25], bi[25];
        if (tid < 25) {
            int idx = c * 25 + tid;
            float s = dg[idx] * rsqrtf(dv[idx] + 1e-5f);
            sc[tid] = s;
            bi[tid] = db[idx] - dm[idx] * s;
        }
        __syncthreads();
        const float* xp = x + (size_t)(n * 64 + c) * TJ;
        for (int i = tid; i < 7500; i += 256) {
            int t = i / 25, v = i - t * 25;
            xsm[v * 304 + t] = xp[i] * sc[v] + bi[v];
        }
        __syncthreads();
        // write 25 rows of 300 floats, fully coalesced
        for (int i = tid; i < 1875; i += 256) {
            int v = i / 75, t4 = i - v * 75;
            ((float4*)(g_xbn + ((size_t)(n * 25 + v) * 64 + c) * Tt))[t4] =
                ((const float4*)(xsm + v * 304))[t4];
        }
    } else {
        int ptid = (blockIdx.x - 1024) * 256 + tid;
        int stride = 8 * 256;
        for (int i = ptid; i < 16 * 600; i += stride) {
            int d = i / 600, m = i - d * 600;
            g_krt[i] = (m <= 598) ? key_rel[m * 16 + d] : 0.f;
        }
        for (int i = ptid; i < 64 * 192; i += stride) {
            int c = i / 192, o = i - c * 192;
            g_Wt[i] = W[o * 64 + c];
        }
        for (int i = ptid; i < 64 * 64; i += stride) {
            int d = i >> 6, o = i & 63;
            g_Wat[i] = Wa[o * 64 + d];
        }
    }
}

// ---------------------------------------------------------------------------
// Kernel 1: 1x1 qkv conv over pre-normalized g_xbn. 3 blocks per b (T split).
// Fill is now a pure float4 copy.
// ---------------------------------------------------------------------------
__global__ void __launch_bounds__(256, 3) qkv_kernel(const float* __restrict__ Wb)
{
    int b = blockIdx.x;
    int T0 = blockIdx.y * 100;
    extern __shared__ float sm[];
    float* xs = sm;             // 64*100
    float* Wt = xs + 6400;      // 12288  [c][o]
    int tid = threadIdx.x;

    for (int i = tid; i < 3072; i += 256)
        ((float4*)Wt)[i] = ((const float4*)g_Wt)[i];
    const float* xb = g_xbn + (size_t)b * 64 * Tt + T0;
    for (int i = tid; i < 1600; i += 256) {
        int c = i / 25, t4 = i - c * 25;
        ((float4*)(xs + c * 100))[t4] = *(const float4*)(xb + c * Tt + t4 * 4);
    }
    __syncthreads();

    for (int task = tid; task < 624; task += 256) {
        int og = task % 48, tg = task / 48;
        int o0 = og * 4, t0 = tg * 8;
        bool full = (tg < 12);
        float acc[4][8];
        #pragma unroll
        for (int i = 0; i < 4; ++i)
            #pragma unroll
            for (int j = 0; j < 8; ++j) acc[i][j] = 0.f;

        if (full) {
            #pragma unroll 8
            for (int c = 0; c < 64; ++c) {
                float4 w4 = *(const float4*)(Wt + c * 192 + o0);
                float4 xa = *(const float4*)(xs + c * 100 + t0);
                float4 xc = *(const float4*)(xs + c * 100 + t0 + 4);
                float wa[4] = {w4.x, w4.y, w4.z, w4.w};
                float A[8] = {xa.x, xa.y, xa.z, xa.w, xc.x, xc.y, xc.z, xc.w};
                #pragma unroll
                for (int i = 0; i < 4; ++i)
                    #pragma unroll
                    for (int j = 0; j < 8; ++j)
                        acc[i][j] += wa[i] * A[j];
            }
        } else {
            #pragma unroll 8
            for (int c = 0; c < 64; ++c) {
                float4 w4 = *(const float4*)(Wt + c * 192 + o0);
                float4 xa = *(const float4*)(xs + c * 100 + t0);
                float wa[4] = {w4.x, w4.y, w4.z, w4.w};
                float A[4] = {xa.x, xa.y, xa.z, xa.w};
                #pragma unroll
                for (int i = 0; i < 4; ++i)
                    #pragma unroll
                    for (int j = 0; j < 4; ++j)
                        acc[i][j] += wa[i] * A[j];
            }
        }

        float* outp = g_qkv + ((size_t)b * QKVO + o0) * Tt + T0 + t0;
        #pragma unroll
        for (int i = 0; i < 4; ++i) {
            float bias = Wb[o0 + i];
            float scale = (o0 + i < 64) ? 0.25f : 1.0f;  // q * DKH^-0.5
            float4 r;
            r.x = (acc[i][0] + bias) * scale;
            r.y = (acc[i][1] + bias) * scale;
            r.z = (acc[i][2] + bias) * scale;
            r.w = (acc[i][3] + bias) * scale;
            *(float4*)(outp + i * Tt) = r;
            if (full) {
                float4 r2;
                r2.x = (acc[i][4] + bias) * scale;
                r2.y = (acc[i][5] + bias) * scale;
                r2.z = (acc[i][6] + bias) * scale;
                r2.w = (acc[i][7] + bias) * scale;
                *(float4*)(outp + i * Tt + 4) = r2;
            }
        }
    }
}

// ---------------------------------------------------------------------------
// Kernel 2: attention per (b,h) — R14 version verbatim.
// ---------------------------------------------------------------------------
#define KST 300   // ks row stride
#define RST 600   // krs row stride

__global__ void __launch_bounds__(ATH, 2) attn_kernel()
{
    int bh = blockIdx.x;
    int b = bh >> 2, h = bh & 3;
    int nn = b / Vv, vv = b - nn * Vv;
    extern __shared__ float sm[];
    float* ks   = sm;                  // 16*300  [d][s]
    float* krs  = ks + 16 * KST;       // 16*600  [d][m]
    float* vt   = krs + 16 * RST;      // 384*16  [s][d] chunk-swizzled

    const float* base = g_qkv + (size_t)b * QKVO * Tt;
    const float* qg = base + (h * 16) * Tt;
    const float* kg = base + (64 + h * 16) * Tt;
    const float* vg = base + (128 + h * 16) * Tt;
    float* og_base = g_attn + ((size_t)nn * 64 + h * 16) * TJ + vv;

    int tid = threadIdx.x;
    for (int i = tid; i < 1200; i += ATH)
        ((float4*)ks)[i] = ((const float4*)kg)[i];
    for (int i = tid; i < 2400; i += ATH)
        ((float4*)krs)[i] = ((const float4*)g_krt)[i];
    for (int i = tid + 4800; i < 6144; i += ATH)
        vt[i] = 0.f;
    for (int i = tid; i < 1200; i += ATH) {
        int s = i >> 2, c = i & 3;
        int w = (s >> 2) & 3;
        float4 vvv;
        vvv.x = vg[(c * 4 + 0) * 300 + s];
        vvv.y = vg[(c * 4 + 1) * 300 + s];
        vvv.z = vg[(c * 4 + 2) * 300 + s];
        vvv.w = vg[(c * 4 + 3) * 300 + s];
        *(float4*)(vt + s * 16 + ((c ^ w) << 2)) = vvv;
    }
    __syncthreads();

    int warp = tid >> 5, lane = tid & 31;
    int lw = lane & 3;
    int oi = (((lane >> 4) & 1) << 1) | ((lane >> 3) & 1);
    int odp = (((lane >> 2) & 1) << 1) | ((lane >> 1) & 1);
    int odb = lane & 1;

    for (int g = warp; g < 75; g += 10) {
        int t0 = g * 4;
        float2 L[3][4][2];
        bool v2 = (lane < 11);
        #pragma unroll
        for (int p = 0; p < 3; ++p) {
            float init = (p < 2 || v2) ? 0.f : -1e30f;
            #pragma unroll
            for (int i = 0; i < 4; ++i) {
                L[p][i][0] = make_float2(init, init);
                L[p][i][1] = make_float2(init, init);
            }
        }

        #pragma unroll
        for (int d = 0; d < 16; ++d) {
            float4 q4 = __ldg((const float4*)(qg + d * 300 + t0));
            float2 qd[4] = { make_float2(q4.x, q4.x), make_float2(q4.y, q4.y),
                             make_float2(q4.z, q4.z), make_float2(q4.w, q4.w) };
            #pragma unroll
            for (int p = 0; p < 3; ++p) {
                if (p < 2 || v2) {
                    int s0 = p * 128 + lane * 4;
                    int m0 = s0 - t0 + 296;
                    float4 k4 = *(const float4*)(ks + d * KST + s0);
                    float4 ra = *(const float4*)(krs + d * RST + m0);
                    float4 rb = *(const float4*)(krs + d * RST + m0 + 4);
                    float2 k01 = make_float2(k4.x, k4.y), k23 = make_float2(k4.z, k4.w);
                    float2 r01 = make_float2(ra.x, ra.y), r23 = make_float2(ra.z, ra.w);
                    float2 r45 = make_float2(rb.x, rb.y);
                    float2 r12 = make_float2(ra.y, ra.z);
                    float2 r34 = make_float2(ra.w, rb.x);
                    float2 r56 = make_float2(rb.y, rb.z);
                    L[p][0][0] = ffma2(qd[0], k01, L[p][0][0]); L[p][0][1] = ffma2(qd[0], k23, L[p][0][1]);
                    L[p][1][0] = ffma2(qd[1], k01, L[p][1][0]); L[p][1][1] = ffma2(qd[1], k23, L[p][1][1]);
                    L[p][2][0] = ffma2(qd[2], k01, L[p][2][0]); L[p][2][1] = ffma2(qd[2], k23, L[p][2][1]);
                    L[p][3][0] = ffma2(qd[3], k01, L[p][3][0]); L[p][3][1] = ffma2(qd[3], k23, L[p][3][1]);
                    L[p][0][0] = ffma2(qd[0], r34, L[p][0][0]); L[p][0][1] = ffma2(qd[0], r56, L[p][0][1]);
                    L[p][1][0] = ffma2(qd[1], r23, L[p][1][0]); L[p][1][1] = ffma2(qd[1], r45, L[p][1][1]);
                    L[p][2][0] = ffma2(qd[2], r12, L[p][2][0]); L[p][2][1] = ffma2(qd[2], r34, L[p][2][1]);
                    L[p][3][0] = ffma2(qd[3], r01, L[p][3][0]); L[p][3][1] = ffma2(qd[3], r23, L[p][3][1]);
                }
            }
        }

        #pragma unroll
        for (int i = 0; i < 4; ++i) {
            float mx = -1e30f;
            #pragma unroll
            for (int p = 0; p < 3; ++p)
                #pragma unroll
                for (int jp = 0; jp < 2; ++jp)
                    mx = fmaxf(mx, fmaxf(L[p][i][jp].x, L[p][i][jp].y));
            #pragma unroll
            for (int o = 16; o > 0; o >>= 1)
                mx = fmaxf(mx, __shfl_xor_sync(0xffffffffu, mx, o));
            float s = 0.f;
            #pragma unroll
            for (int p = 0; p < 3; ++p)
                #pragma unroll
                for (int jp = 0; jp < 2; ++jp) {
                    float ex = __expf(L[p][i][jp].x - mx);
                    float ey = __expf(L[p][i][jp].y - mx);
                    L[p][i][jp] = make_float2(ex, ey);
                    s += ex + ey;
                }
            #pragma unroll
            for (int o = 16; o > 0; o >>= 1)
                s += __shfl_xor_sync(0xffffffffu, s, o);
            float inv = 1.f / s;
            float2 inv2 = make_float2(inv, inv);
            #pragma unroll
            for (int p = 0; p < 3; ++p)
                #pragma unroll
                for (int jp = 0; jp < 2; ++jp)
                    L[p][i][jp] = fmul2(L[p][i][jp], inv2);
        }

        #pragma unroll
        for (int sweep = 0; sweep < 2; ++sweep) {
            float2 r[16];
            #pragma unroll
            for (int k = 0; k < 16; ++k) r[k] = make_float2(0.f, 0.f);

            #pragma unroll
            for (int p = 0; p < 3; ++p) {
                int sbase = p * 128 + lane * 4;
                #pragma unroll
                for (int j = 0; j < 4; ++j) {
                    const float* vp = vt + (sbase + j) * 16;
                    float4 va = *(const float4*)(vp + (((sweep * 2)     ^ lw) << 2));
                    float4 vb = *(const float4*)(vp + (((sweep * 2 + 1) ^ lw) << 2));
                    float2 v01 = make_float2(va.x, va.y);
                    float2 v23 = make_float2(va.z, va.w);
                    float2 v45 = make_float2(vb.x, vb.y);
                    float2 v67 = make_float2(vb.z, vb.w);
                    #pragma unroll
                    for (int i = 0; i < 4; ++i) {
                        float pij = (j & 1) ? L[p][i][j >> 1].y : L[p][i][j >> 1].x;
                        float2 pp = make_float2(pij, pij);
                        r[i * 4 + 0] = ffma2(pp, v01, r[i * 4 + 0]);
                        r[i * 4 + 1] = ffma2(pp, v23, r[i * 4 + 1]);
                        r[i * 4 + 2] = ffma2(pp, v45, r[i * 4 + 2]);
                        r[i * 4 + 3] = ffma2(pp, v67, r[i * 4 + 3]);
                    }
                }
            }

            bool hi;
            hi = (lane & 16);
            #pragma unroll
            for (int k = 0; k < 8; ++k) {
                float2 keep = hi ? r[k + 8] : r[k];
                float2 send = hi ? r[k] : r[k + 8];
                keep.x += __shfl_xor_sync(0xffffffffu, send.x, 16);
                keep.y += __shfl_xor_sync(0xffffffffu, send.y, 16);
                r[k] = keep;
            }
            hi = (lane & 8);
            #pragma unroll
            for (int k = 0; k < 4; ++k) {
                float2 keep = hi ? r[k + 4] : r[k];
                float2 send = hi ? r[k] : r[k + 4];
                keep.x += __shfl_xor_sync(0xffffffffu, send.x, 8);
                keep.y += __shfl_xor_sync(0xffffffffu, send.y, 8);
                r[k] = keep;
            }
            hi = (lane & 4);
            #pragma unroll
            for (int k = 0; k < 2; ++k) {
                float2 keep = hi ? r[k + 2] : r[k];
                float2 send = hi ? r[k] : r[k + 2];
                keep.x += __shfl_xor_sync(0xffffffffu, send.x, 4);
                keep.y += __shfl_xor_sync(0xffffffffu, send.y, 4);
                r[k] = keep;
            }
            hi = (lane & 2);
            {
                float2 keep = hi ? r[1] : r[0];
                float2 send = hi ? r[0] : r[1];
                keep.x += __shfl_xor_sync(0xffffffffu, send.x, 2);
                keep.y += __shfl_xor_sync(0xffffffffu, send.y, 2);
                r[0] = keep;
            }
            {
                bool hb = (lane & 1);
                float keep = hb ? r[0].y : r[0].x;
                float send = hb ? r[0].x : r[0].y;
                float outv = keep + __shfl_xor_sync(0xffffffffu, send, 1);
                int d = sweep * 8 + odp * 2 + odb;
                og_base[(size_t)d * TJ + (t0 + oi) * 25] = outv;
            }
        }
    }
}

// ---------------------------------------------------------------------------
// Kernel 3: proj — dense GEMM over j = t*25+v (R13 version).
// ---------------------------------------------------------------------------
__global__ void __launch_bounds__(256, 2) proj_kernel(
    const float* __restrict__ Ba,
    const float* __restrict__ bg, const float* __restrict__ bb,
    const float* __restrict__ bm, const float* __restrict__ bv,
    const float* __restrict__ x, float* __restrict__ out)
{
    int n = blockIdx.x;
    int jt = blockIdx.y;
    int j0 = jt * 300;
    extern __shared__ float sm[];
    float* as = sm;            // 64*304  [d][jj]
    float* Wt = as + 64 * 304; // 64*64   [d][o]
    float* s2 = Wt + 4096;     // 64
    float* b2 = s2 + 64;       // 64
    int tid = threadIdx.x;

    for (int i = tid; i < 4800; i += 256) {
        int d = i / 75, r = i - d * 75;
        ((float4*)(as + d * 304))[r] =
            ((const float4*)(g_attn + (size_t)(n * 64 + d) * TJ + j0))[r];
    }
    for (int i = tid; i < 256; i += 256) {
        int d = i >> 2;
        as[d * 304 + 300 + (i & 3)] = 0.f;
    }
    for (int i = tid; i < 1024; i += 256)
        ((float4*)Wt)[i] = ((const float4*)g_Wat)[i];
    if (tid < 64) {
        float s = bg[tid] * rsqrtf(bv[tid] + 1e-5f);
        s2[tid] = s;
        b2[tid] = bb[tid] - bm[tid] * s;
    }
    __syncthreads();

    const float* xb = x + (size_t)n * 64 * TJ + j0;
    float*       ob = out + (size_t)n * 64 * TJ + j0;

    for (int task = tid; task < 608; task += 256) {
        int og = task & 15, jg = task >> 4;
        int o0 = og * 4, jj0 = jg * 8;
        bool full = (jg < 37);
        float acc[4][8];
        #pragma unroll
        for (int i = 0; i < 4; ++i)
            #pragma unroll
            for (int j = 0; j < 8; ++j) acc[i][j] = 0.f;

        #pragma unroll 8
        for (int d = 0; d < 64; ++d) {
            float4 w4 = *(const float4*)(Wt + d * 64 + o0);
            float4 aa = *(const float4*)(as + d * 304 + jj0);
            float4 ac = *(const float4*)(as + d * 304 + jj0 + 4);
            float wa[4] = {w4.x, w4.y, w4.z, w4.w};
            float A[8] = {aa.x, aa.y, aa.z, aa.w, ac.x, ac.y, ac.z, ac.w};
            #pragma unroll
            for (int i = 0; i < 4; ++i)
                #pragma unroll
                for (int j = 0; j < 8; ++j)
                    acc[i][j] += wa[i] * A[j];
        }
        #pragma unroll
        for (int i = 0; i < 4; ++i) {
            int o = o0 + i;
            float bias = Ba[o];
            float ss = s2[o], bb2 = b2[o];
            const float* xo = xb + (size_t)o * TJ + jj0;
            float*       oo = ob + (size_t)o * TJ + jj0;
            float4 xv = *(const float4*)(xo);
            float4 r;
            r.x = fmaxf((acc[i][0] + bias + xv.x) * ss + bb2, 0.f);
            r.y = fmaxf((acc[i][1] + bias + xv.y) * ss + bb2, 0.f);
            r.z = fmaxf((acc[i][2] + bias + xv.z) * ss + bb2, 0.f);
            r.w = fmaxf((acc[i][3] + bias + xv.w) * ss + bb2, 0.f);
            *(float4*)(oo) = r;
            if (full) {
                float4 xw = *(const float4*)(xo + 4);
                float4 r2;
                r2.x = fmaxf((acc[i][4] + bias + xw.x) * ss + bb2, 0.f);
                r2.y = fmaxf((acc[i][5] + bias + xw.y) * ss + bb2, 0.f);
                r2.z = fmaxf((acc[i][6] + bias + xw.z) * ss + bb2, 0.f);
                r2.w = fmaxf((acc[i][7] + bias + xw.w) * ss + bb2, 0.f);
                *(float4*)(oo + 4) = r2;
            }
        }
    }
}

// ---------------------------------------------------------------------------
extern "C" void kernel_launch(void* const* d_in, const int* in_sizes, int n_in,
                              void* d_out, int out_size)
{
    const float* x       = (const float*)d_in[0];
    const float* dbn_g   = (const float*)d_in[1];
    const float* dbn_b   = (const float*)d_in[2];
    const float* dbn_m   = (const float*)d_in[3];
    const float* dbn_v   = (const float*)d_in[4];
    const float* qkv_w   = (const float*)d_in[5];
    const float* qkv_b   = (const float*)d_in[6];
    const float* key_rel = (const float*)d_in[7];
    const float* attn_w  = (const float*)d_in[8];
    const float* attn_b  = (const float*)d_in[9];
    const float* bn_g    = (const float*)d_in[10];
    const float* bn_b    = (const float*)d_in[11];
    const float* bn_m    = (const float*)d_in[12];
    const float* bn_v    = (const float*)d_in[13];
    float* out = (float*)d_out;

    const int SM1 = (6400 + 12288) * 4;                    // 74,752
    const int SM2 = (16 * KST + 16 * RST + 384 * 16) * 4;  // 82,176
    const int SM3 = (64 * 304 + 4096 + 128) * 4;           // 94,720

    cudaFuncSetAttribute(qkv_kernel,  cudaFuncAttributeMaxDynamicSharedMemorySize, SM1);
    cudaFuncSetAttribute(attn_kernel, cudaFuncAttributeMaxDynamicSharedMemorySize, SM2);
    cudaFuncSetAttribute(proj_kernel, cudaFuncAttributeMaxDynamicSharedMemorySize, SM3);

    setup_kernel<<<1032, 256>>>(x, dbn_g, dbn_b, dbn_m, dbn_v, key_rel, qkv_w, attn_w);
    qkv_kernel<<<dim3(Bb, 3), 256, SM1>>>(qkv_b);
    attn_kernel<<<Bb * NHh, ATH, SM2>>>();
    proj_kernel<<<dim3(Nn, 25), 256, SM3>>>(attn_b, bn_g, bn_b, bn_m, bn_v, x, out);
}

// round 16
// speedup vs baseline: 1.3665x; 1.0019x over previous
#include <cuda_runtime.h>
#include <cuda_bf16.h>
#include <math.h>

#define Nn 16
#define Cc 64
#define Tt 300
#define Vv 25
#define NHh 4
#define Bb (Nn*Vv)          // 400
#define QKVO 192            // 2*DK+DV
#define TJ (Tt*Vv)          // 7500
#define ATH 320             // attn threads per block (10 warps)

__device__ float g_qkv[(size_t)Bb * QKVO * Tt];
__device__ float g_attn[(size_t)Nn * 64 * TJ];   // [n][d][t*25+v]
__device__ float g_xbn[(size_t)Bb * 64 * Tt];    // dbn-normalized x, [b][c][t]
__device__ float g_krt[16 * 600];   // key_rel transposed+padded, [d][m]
__device__ float g_Wt[64 * 192];    // qkv_w transposed, [c][o]
__device__ float g_Wat[64 * 64];    // attn_w transposed, [d][o]

// ---- packed fp32 helpers (FFMA2 / FMUL2 are PTX-only on sm_103a) ----
__device__ __forceinline__ float2 ffma2(float2 a, float2 b, float2 c) {
    unsigned long long A = *(unsigned long long*)&a;
    unsigned long long B = *(unsigned long long*)&b;
    unsigned long long C = *(unsigned long long*)&c;
    unsigned long long D;
    asm("fma.rn.f32x2 %0, %1, %2, %3;" : "=l"(D) : "l"(A), "l"(B), "l"(C));
    return *(float2*)&D;
}
__device__ __forceinline__ float2 fmul2(float2 a, float2 b) {
    unsigned long long A = *(unsigned long long*)&a;
    unsigned long long B = *(unsigned long long*)&b;
    unsigned long long D;
    asm("mul.rn.f32x2 %0, %1, %2;" : "=l"(D) : "l"(A), "l"(B));
    return *(float2*)&D;
}

// ---------------------------------------------------------------------------
// Kernel 0: setup. Blocks 0..1023: dbn + transpose x -> g_xbn. Blocks 1024+:
// one-time weight/key_rel transposes.
// ---------------------------------------------------------------------------
__global__ void setup_kernel(const float* __restrict__ x,
                             const float* __restrict__ dg, const float* __restrict__ db,
                             const float* __restrict__ dm, const float* __restrict__ dv,
                             const float* __restrict__ key_rel,
                             const float* __restrict__ W,
                             const float* __restrict__ Wa)
{
    int tid = threadIdx.x;
    if (blockIdx.x < 1024) {
        int n = blockIdx.x >> 6, c = blockIdx.x & 63;
        __shared__ float xsm[25 * 304];
        __shared__ float sc[25], bi[25];
        if (tid < 25) {
            int idx = c * 25 + tid;
            float s = dg[idx] * rsqrtf(dv[idx] + 1e-5f);
            sc[tid] = s;
            bi[tid] = db[idx] - dm[idx] * s;
        }
        __syncthreads();
        const float* xp = x + (size_t)(n * 64 + c) * TJ;
        for (int i = tid; i < 7500; i += 256) {
            int t = i / 25, v = i - t * 25;
            xsm[v * 304 + t] = xp[i] * sc[v] + bi[v];
        }
        __syncthreads();
        for (int i = tid; i < 1875; i += 256) {
            int v = i / 75, t4 = i - v * 75;
            ((float4*)(g_xbn + ((size_t)(n * 25 + v) * 64 + c) * Tt))[t4] =
                ((const float4*)(xsm + v * 304))[t4];
        }
    } else {
        int ptid = (blockIdx.x - 1024) * 256 + tid;
        int stride = 8 * 256;
        for (int i = ptid; i < 16 * 600; i += stride) {
            int d = i / 600, m = i - d * 600;
            g_krt[i] = (m <= 598) ? key_rel[m * 16 + d] : 0.f;
        }
        for (int i = ptid; i < 64 * 192; i += stride) {
            int c = i / 192, o = i - c * 192;
            g_Wt[i] = W[o * 64 + c];
        }
        for (int i = ptid; i < 64 * 64; i += stride) {
            int d = i >> 6, o = i & 63;
            g_Wat[i] = Wa[o * 64 + d];
        }
    }
}

// ---------------------------------------------------------------------------
// Kernel 1: 1x1 qkv conv over pre-normalized g_xbn (R15 version).
// ---------------------------------------------------------------------------
__global__ void __launch_bounds__(256, 3) qkv_kernel(const float* __restrict__ Wb)
{
    int b = blockIdx.x;
    int T0 = blockIdx.y * 100;
    extern __shared__ float sm[];
    float* xs = sm;             // 64*100
    float* Wt = xs + 6400;      // 12288  [c][o]
    int tid = threadIdx.x;

    for (int i = tid; i < 3072; i += 256)
        ((float4*)Wt)[i] = ((const float4*)g_Wt)[i];
    const float* xb = g_xbn + (size_t)b * 64 * Tt + T0;
    for (int i = tid; i < 1600; i += 256) {
        int c = i / 25, t4 = i - c * 25;
        ((float4*)(xs + c * 100))[t4] = *(const float4*)(xb + c * Tt + t4 * 4);
    }
    __syncthreads();

    for (int task = tid; task < 624; task += 256) {
        int og = task % 48, tg = task / 48;
        int o0 = og * 4, t0 = tg * 8;
        bool full = (tg < 12);
        float acc[4][8];
        #pragma unroll
        for (int i = 0; i < 4; ++i)
            #pragma unroll
            for (int j = 0; j < 8; ++j) acc[i][j] = 0.f;

        if (full) {
            #pragma unroll 8
            for (int c = 0; c < 64; ++c) {
                float4 w4 = *(const float4*)(Wt + c * 192 + o0);
                float4 xa = *(const float4*)(xs + c * 100 + t0);
                float4 xc = *(const float4*)(xs + c * 100 + t0 + 4);
                float wa[4] = {w4.x, w4.y, w4.z, w4.w};
                float A[8] = {xa.x, xa.y, xa.z, xa.w, xc.x, xc.y, xc.z, xc.w};
                #pragma unroll
                for (int i = 0; i < 4; ++i)
                    #pragma unroll
                    for (int j = 0; j < 8; ++j)
                        acc[i][j] += wa[i] * A[j];
            }
        } else {
            #pragma unroll 8
            for (int c = 0; c < 64; ++c) {
                float4 w4 = *(const float4*)(Wt + c * 192 + o0);
                float4 xa = *(const float4*)(xs + c * 100 + t0);
                float wa[4] = {w4.x, w4.y, w4.z, w4.w};
                float A[4] = {xa.x, xa.y, xa.z, xa.w};
                #pragma unroll
                for (int i = 0; i < 4; ++i)
                    #pragma unroll
                    for (int j = 0; j < 4; ++j)
                        acc[i][j] += wa[i] * A[j];
            }
        }

        float* outp = g_qkv + ((size_t)b * QKVO + o0) * Tt + T0 + t0;
        #pragma unroll
        for (int i = 0; i < 4; ++i) {
            float bias = Wb[o0 + i];
            float scale = (o0 + i < 64) ? 0.25f : 1.0f;  // q * DKH^-0.5
            float4 r;
            r.x = (acc[i][0] + bias) * scale;
            r.y = (acc[i][1] + bias) * scale;
            r.z = (acc[i][2] + bias) * scale;
            r.w = (acc[i][3] + bias) * scale;
            *(float4*)(outp + i * Tt) = r;
            if (full) {
                float4 r2;
                r2.x = (acc[i][4] + bias) * scale;
                r2.y = (acc[i][5] + bias) * scale;
                r2.z = (acc[i][6] + bias) * scale;
                r2.w = (acc[i][7] + bias) * scale;
                *(float4*)(outp + i * Tt + 4) = r2;
            }
        }
    }
}

// ---------------------------------------------------------------------------
// Kernel 2: attention per (b,h). R15 core + base-2 softmax: log2(e) folded
// into the q load (q only feeds logits), exp via exp2f (bare EX2).
// ---------------------------------------------------------------------------
#define KST 300   // ks row stride
#define RST 600   // krs row stride
#define LOG2E 1.4426950408889634f

__global__ void __launch_bounds__(ATH, 2) attn_kernel()
{
    int bh = blockIdx.x;
    int b = bh >> 2, h = bh & 3;
    int nn = b / Vv, vv = b - nn * Vv;
    extern __shared__ float sm[];
    float* ks   = sm;                  // 16*300  [d][s]
    float* krs  = ks + 16 * KST;       // 16*600  [d][m]
    float* vt   = krs + 16 * RST;      // 384*16  [s][d] chunk-swizzled

    const float* base = g_qkv + (size_t)b * QKVO * Tt;
    const float* qg = base + (h * 16) * Tt;
    const float* kg = base + (64 + h * 16) * Tt;
    const float* vg = base + (128 + h * 16) * Tt;
    float* og_base = g_attn + ((size_t)nn * 64 + h * 16) * TJ + vv;

    int tid = threadIdx.x;
    for (int i = tid; i < 1200; i += ATH)
        ((float4*)ks)[i] = ((const float4*)kg)[i];
    for (int i = tid; i < 2400; i += ATH)
        ((float4*)krs)[i] = ((const float4*)g_krt)[i];
    for (int i = tid + 4800; i < 6144; i += ATH)
        vt[i] = 0.f;
    for (int i = tid; i < 1200; i += ATH) {
        int s = i >> 2, c = i & 3;
        int w = (s >> 2) & 3;
        float4 vvv;
        vvv.x = vg[(c * 4 + 0) * 300 + s];
        vvv.y = vg[(c * 4 + 1) * 300 + s];
        vvv.z = vg[(c * 4 + 2) * 300 + s];
        vvv.w = vg[(c * 4 + 3) * 300 + s];
        *(float4*)(vt + s * 16 + ((c ^ w) << 2)) = vvv;
    }
    __syncthreads();

    int warp = tid >> 5, lane = tid & 31;
    int lw = lane & 3;
    int oi = (((lane >> 4) & 1) << 1) | ((lane >> 3) & 1);
    int odp = (((lane >> 2) & 1) << 1) | ((lane >> 1) & 1);
    int odb = lane & 1;

    for (int g = warp; g < 75; g += 10) {
        int t0 = g * 4;
        float2 L[3][4][2];
        bool v2 = (lane < 11);
        #pragma unroll
        for (int p = 0; p < 3; ++p) {
            float init = (p < 2 || v2) ? 0.f : -1e30f;
            #pragma unroll
            for (int i = 0; i < 4; ++i) {
                L[p][i][0] = make_float2(init, init);
                L[p][i][1] = make_float2(init, init);
            }
        }

        #pragma unroll
        for (int d = 0; d < 16; ++d) {
            float4 q4 = __ldg((const float4*)(qg + d * 300 + t0));
            // fold log2(e): softmax computed in base 2 (mathematically identical)
            float2 qd[4] = { make_float2(q4.x * LOG2E, q4.x * LOG2E),
                             make_float2(q4.y * LOG2E, q4.y * LOG2E),
                             make_float2(q4.z * LOG2E, q4.z * LOG2E),
                             make_float2(q4.w * LOG2E, q4.w * LOG2E) };
            #pragma unroll
            for (int p = 0; p < 3; ++p) {
                if (p < 2 || v2) {
                    int s0 = p * 128 + lane * 4;
                    int m0 = s0 - t0 + 296;
                    float4 k4 = *(const float4*)(ks + d * KST + s0);
                    float4 ra = *(const float4*)(krs + d * RST + m0);
                    float4 rb = *(const float4*)(krs + d * RST + m0 + 4);
                    float2 k01 = make_float2(k4.x, k4.y), k23 = make_float2(k4.z, k4.w);
                    float2 r01 = make_float2(ra.x, ra.y), r23 = make_float2(ra.z, ra.w);
                    float2 r45 = make_float2(rb.x, rb.y);
                    float2 r12 = make_float2(ra.y, ra.z);
                    float2 r34 = make_float2(ra.w, rb.x);
                    float2 r56 = make_float2(rb.y, rb.z);
                    L[p][0][0] = ffma2(qd[0], k01, L[p][0][0]); L[p][0][1] = ffma2(qd[0], k23, L[p][0][1]);
                    L[p][1][0] = ffma2(qd[1], k01, L[p][1][0]); L[p][1][1] = ffma2(qd[1], k23, L[p][1][1]);
                    L[p][2][0] = ffma2(qd[2], k01, L[p][2][0]); L[p][2][1] = ffma2(qd[2], k23, L[p][2][1]);
                    L[p][3][0] = ffma2(qd[3], k01, L[p][3][0]); L[p][3][1] = ffma2(qd[3], k23, L[p][3][1]);
                    L[p][0][0] = ffma2(qd[0], r34, L[p][0][0]); L[p][0][1] = ffma2(qd[0], r56, L[p][0][1]);
                    L[p][1][0] = ffma2(qd[1], r23, L[p][1][0]); L[p][1][1] = ffma2(qd[1], r45, L[p][1][1]);
                    L[p][2][0] = ffma2(qd[2], r12, L[p][2][0]); L[p][2][1] = ffma2(qd[2], r34, L[p][2][1]);
                    L[p][3][0] = ffma2(qd[3], r01, L[p][3][0]); L[p][3][1] = ffma2(qd[3], r23, L[p][3][1]);
                }
            }
        }

        #pragma unroll
        for (int i = 0; i < 4; ++i) {
            float mx = -1e30f;
            #pragma unroll
            for (int p = 0; p < 3; ++p)
                #pragma unroll
                for (int jp = 0; jp < 2; ++jp)
                    mx = fmaxf(mx, fmaxf(L[p][i][jp].x, L[p][i][jp].y));
            #pragma unroll
            for (int o = 16; o > 0; o >>= 1)
                mx = fmaxf(mx, __shfl_xor_sync(0xffffffffu, mx, o));
            float s = 0.f;
            #pragma unroll
            for (int p = 0; p < 3; ++p)
                #pragma unroll
                for (int jp = 0; jp < 2; ++jp) {
                    float ex = exp2f(L[p][i][jp].x - mx);
                    float ey = exp2f(L[p][i][jp].y - mx);
                    L[p][i][jp] = make_float2(ex, ey);
                    s += ex + ey;
                }
            #pragma unroll
            for (int o = 16; o > 0; o >>= 1)
                s += __shfl_xor_sync(0xffffffffu, s, o);
            float inv = 1.f / s;
            float2 inv2 = make_float2(inv, inv);
            #pragma unroll
            for (int p = 0; p < 3; ++p)
                #pragma unroll
                for (int jp = 0; jp < 2; ++jp)
                    L[p][i][jp] = fmul2(L[p][i][jp], inv2);
        }

        #pragma unroll
        for (int sweep = 0; sweep < 2; ++sweep) {
            float2 r[16];
            #pragma unroll
            for (int k = 0; k < 16; ++k) r[k] = make_float2(0.f, 0.f);

            #pragma unroll
            for (int p = 0; p < 3; ++p) {
                int sbase = p * 128 + lane * 4;
                #pragma unroll
                for (int j = 0; j < 4; ++j) {
                    const float* vp = vt + (sbase + j) * 16;
                    float4 va = *(const float4*)(vp + (((sweep * 2)     ^ lw) << 2));
                    float4 vb = *(const float4*)(vp + (((sweep * 2 + 1) ^ lw) << 2));
                    float2 v01 = make_float2(va.x, va.y);
                    float2 v23 = make_float2(va.z, va.w);
                    float2 v45 = make_float2(vb.x, vb.y);
                    float2 v67 = make_float2(vb.z, vb.w);
                    #pragma unroll
                    for (int i = 0; i < 4; ++i) {
                        float pij = (j & 1) ? L[p][i][j >> 1].y : L[p][i][j >> 1].x;
                        float2 pp = make_float2(pij, pij);
                        r[i * 4 + 0] = ffma2(pp, v01, r[i * 4 + 0]);
                        r[i * 4 + 1] = ffma2(pp, v23, r[i * 4 + 1]);
                        r[i * 4 + 2] = ffma2(pp, v45, r[i * 4 + 2]);
                        r[i * 4 + 3] = ffma2(pp, v67, r[i * 4 + 3]);
                    }
                }
            }

            bool hi;
            hi = (lane & 16);
            #pragma unroll
            for (int k = 0; k < 8; ++k) {
                float2 keep = hi ? r[k + 8] : r[k];
                float2 send = hi ? r[k] : r[k + 8];
                keep.x += __shfl_xor_sync(0xffffffffu, send.x, 16);
                keep.y += __shfl_xor_sync(0xffffffffu, send.y, 16);
                r[k] = keep;
            }
            hi = (lane & 8);
            #pragma unroll
            for (int k = 0; k < 4; ++k) {
                float2 keep = hi ? r[k + 4] : r[k];
                float2 send = hi ? r[k] : r[k + 4];
                keep.x += __shfl_xor_sync(0xffffffffu, send.x, 8);
                keep.y += __shfl_xor_sync(0xffffffffu, send.y, 8);
                r[k] = keep;
            }
            hi = (lane & 4);
            #pragma unroll
            for (int k = 0; k < 2; ++k) {
                float2 keep = hi ? r[k + 2] : r[k];
                float2 send = hi ? r[k] : r[k + 2];
                keep.x += __shfl_xor_sync(0xffffffffu, send.x, 4);
                keep.y += __shfl_xor_sync(0xffffffffu, send.y, 4);
                r[k] = keep;
            }
            hi = (lane & 2);
            {
                float2 keep = hi ? r[1] : r[0];
                float2 send = hi ? r[0] : r[1];
                keep.x += __shfl_xor_sync(0xffffffffu, send.x, 2);
                keep.y += __shfl_xor_sync(0xffffffffu, send.y, 2);
                r[0] = keep;
            }
            {
                bool hb = (lane & 1);
                float keep = hb ? r[0].y : r[0].x;
                float send = hb ? r[0].x : r[0].y;
                float outv = keep + __shfl_xor_sync(0xffffffffu, send, 1);
                int d = sweep * 8 + odp * 2 + odb;
                og_base[(size_t)d * TJ + (t0 + oi) * 25] = outv;
            }
        }
    }
}

// ---------------------------------------------------------------------------
// Kernel 3: proj v3 — half-j-tiles (152/148), 4o x 4j register tile,
// 56KB smem -> 4 CTA/SM (32 warps). Grid (n, 25, 2).
// ---------------------------------------------------------------------------
__global__ void __launch_bounds__(256, 4) proj_kernel(
    const float* __restrict__ Ba,
    const float* __restrict__ bg, const float* __restrict__ bb,
    const float* __restrict__ bm, const float* __restrict__ bv,
    const float* __restrict__ x, float* __restrict__ out)
{
    int n = blockIdx.x;
    int jt = blockIdx.y;
    int half = blockIdx.z;
    int j0 = jt * 300 + half * 152;        // 152*4B = 608B, 16B-aligned
    int JL = half ? 148 : 152;
    extern __shared__ float sm[];
    float* as = sm;            // 64*152  [d][jj]
    float* Wt = as + 64 * 152; // 64*64   [d][o]
    float* s2 = Wt + 4096;     // 64
    float* b2 = s2 + 64;       // 64
    int tid = threadIdx.x;

    int nf4 = JL >> 2;   // 38 or 37
    for (int i = tid; i < 64 * nf4; i += 256) {
        int d = i / nf4, r = i - d * nf4;
        ((float4*)(as + d * 152))[r] =
            ((const float4*)(g_attn + (size_t)(n * 64 + d) * TJ + j0))[r];
    }
    if (half) {  // zero pad jj 148..151
        for (int i = tid; i < 256; i += 256) {
            int d = i >> 2;
            as[d * 152 + 148 + (i & 3)] = 0.f;
        }
    }
    for (int i = tid; i < 1024; i += 256)
        ((float4*)Wt)[i] = ((const float4*)g_Wat)[i];
    if (tid < 64) {
        float s = bg[tid] * rsqrtf(bv[tid] + 1e-5f);
        s2[tid] = s;
        b2[tid] = bb[tid] - bm[tid] * s;
    }
    __syncthreads();

    const float* xb = x + (size_t)n * 64 * TJ + j0;
    float*       ob = out + (size_t)n * 64 * TJ + j0;

    // 608 tasks: og = task % 16 (fastest), jg = task / 16 (0..37); jj0 = jg*4
    for (int task = tid; task < 608; task += 256) {
        int og = task & 15, jg = task >> 4;
        int o0 = og * 4, jj0 = jg * 4;
        float acc[4][4] = {};
        #pragma unroll 8
        for (int d = 0; d < 64; ++d) {
            float4 w4 = *(const float4*)(Wt + d * 64 + o0);
            float4 a4 = *(const float4*)(as + d * 152 + jj0);
            float wa[4] = {w4.x, w4.y, w4.z, w4.w};
            float aa[4] = {a4.x, a4.y, a4.z, a4.w};
            #pragma unroll
            for (int i = 0; i < 4; ++i)
                #pragma unroll
                for (int j = 0; j < 4; ++j)
                    acc[i][j] += wa[i] * aa[j];
        }
        bool valid = (jj0 < JL);   // jg==37 on half==1 is padding-only
        if (valid) {
            #pragma unroll
            for (int i = 0; i < 4; ++i) {
                int o = o0 + i;
                float bias = Ba[o];
                float ss = s2[o], bb2 = b2[o];
                const float* xo = xb + (size_t)o * TJ + jj0;
                float*       oo = ob + (size_t)o * TJ + jj0;
                float4 xv = *(const float4*)(xo);
                float4 r;
                r.x = fmaxf((acc[i][0] + bias + xv.x) * ss + bb2, 0.f);
                r.y = fmaxf((acc[i][1] + bias + xv.y) * ss + bb2, 0.f);
                r.z = fmaxf((acc[i][2] + bias + xv.z) * ss + bb2, 0.f);
                r.w = fmaxf((acc[i][3] + bias + xv.w) * ss + bb2, 0.f);
                *(float4*)(oo) = r;
            }
        }
    }
}

// ---------------------------------------------------------------------------
extern "C" void kernel_launch(void* const* d_in, const int* in_sizes, int n_in,
                              void* d_out, int out_size)
{
    const float* x       = (const float*)d_in[0];
    const float* dbn_g   = (const float*)d_in[1];
    const float* dbn_b   = (const float*)d_in[2];
    const float* dbn_m   = (const float*)d_in[3];
    const float* dbn_v   = (const float*)d_in[4];
    const float* qkv_w   = (const float*)d_in[5];
    const float* qkv_b   = (const float*)d_in[6];
    const float* key_rel = (const float*)d_in[7];
    const float* attn_w  = (const float*)d_in[8];
    const float* attn_b  = (const float*)d_in[9];
    const float* bn_g    = (const float*)d_in[10];
    const float* bn_b    = (const float*)d_in[11];
    const float* bn_m    = (const float*)d_in[12];
    const float* bn_v    = (const float*)d_in[13];
    float* out = (float*)d_out;

    const int SM1 = (6400 + 12288) * 4;                    // 74,752
    const int SM2 = (16 * KST + 16 * RST + 384 * 16) * 4;  // 82,176
    const int SM3 = (64 * 152 + 4096 + 128) * 4;           // 55,808

    cudaFuncSetAttribute(qkv_kernel,  cudaFuncAttributeMaxDynamicSharedMemorySize, SM1);
    cudaFuncSetAttribute(attn_kernel, cudaFuncAttributeMaxDynamicSharedMemorySize, SM2);
    cudaFuncSetAttribute(proj_kernel, cudaFuncAttributeMaxDynamicSharedMemorySize, SM3);

    setup_kernel<<<1032, 256>>>(x, dbn_g, dbn_b, dbn_m, dbn_v, key_rel, qkv_w, attn_w);
    qkv_kernel<<<dim3(Bb, 3), 256, SM1>>>(qkv_b);
    attn_kernel<<<Bb * NHh, ATH, SM2>>>();
    proj_kernel<<<dim3(Nn, 25, 2), 256, SM3>>>(attn_b, bn_g, bn_b, bn_m, bn_v, x, out);
}

// round 17
// speedup vs baseline: 1.4308x; 1.0471x over previous
#include <cuda_runtime.h>
#include <cuda_bf16.h>
#include <math.h>

#define Nn 16
#define Cc 64
#define Tt 300
#define Vv 25
#define NHh 4
#define Bb (Nn*Vv)          // 400
#define QKVO 192            // 2*DK+DV
#define TJ (Tt*Vv)          // 7500
#define ATH 320             // attn threads per block (10 warps)

__device__ float g_qkv[(size_t)Bb * QKVO * Tt];
__device__ float g_attn[(size_t)Nn * 64 * TJ];   // [n][d][t*25+v]
__device__ float g_xbn[(size_t)Bb * 64 * Tt];    // dbn-normalized x, [b][c][t]
__device__ float g_krt[16 * 600];   // key_rel transposed+padded, [d][m]
__device__ float g_Wt[64 * 192];    // qkv_w transposed, [c][o]
__device__ float g_Wat[64 * 64];    // attn_w transposed, [d][o]

// ---- packed fp32 helpers (FFMA2 / FMUL2 are PTX-only on sm_103a) ----
__device__ __forceinline__ float2 ffma2(float2 a, float2 b, float2 c) {
    unsigned long long A = *(unsigned long long*)&a;
    unsigned long long B = *(unsigned long long*)&b;
    unsigned long long C = *(unsigned long long*)&c;
    unsigned long long D;
    asm("fma.rn.f32x2 %0, %1, %2, %3;" : "=l"(D) : "l"(A), "l"(B), "l"(C));
    return *(float2*)&D;
}
__device__ __forceinline__ float2 fmul2(float2 a, float2 b) {
    unsigned long long A = *(unsigned long long*)&a;
    unsigned long long B = *(unsigned long long*)&b;
    unsigned long long D;
    asm("mul.rn.f32x2 %0, %1, %2;" : "=l"(D) : "l"(A), "l"(B));
    return *(float2*)&D;
}

// ---------------------------------------------------------------------------
// Kernel 0: setup. Blocks 0..1023: dbn + transpose x -> g_xbn. Blocks 1024+:
// one-time weight/key_rel transposes.
// ---------------------------------------------------------------------------
__global__ void setup_kernel(const float* __restrict__ x,
                             const float* __restrict__ dg, const float* __restrict__ db,
                             const float* __restrict__ dm, const float* __restrict__ dv,
                             const float* __restrict__ key_rel,
                             const float* __restrict__ W,
                             const float* __restrict__ Wa)
{
    int tid = threadIdx.x;
    if (blockIdx.x < 1024) {
        int n = blockIdx.x >> 6, c = blockIdx.x & 63;
        __shared__ float xsm[25 * 304];
        __shared__ float sc[25], bi[25];
        if (tid < 25) {
            int idx = c * 25 + tid;
            float s = dg[idx] * rsqrtf(dv[idx] + 1e-5f);
            sc[tid] = s;
            bi[tid] = db[idx] - dm[idx] * s;
        }
        __syncthreads();
        const float* xp = x + (size_t)(n * 64 + c) * TJ;
        for (int i = tid; i < 7500; i += 256) {
            int t = i / 25, v = i - t * 25;
            xsm[v * 304 + t] = xp[i] * sc[v] + bi[v];
        }
        __syncthreads();
        for (int i = tid; i < 1875; i += 256) {
            int v = i / 75, t4 = i - v * 75;
            ((float4*)(g_xbn + ((size_t)(n * 25 + v) * 64 + c) * Tt))[t4] =
                ((const float4*)(xsm + v * 304))[t4];
        }
    } else {
        int ptid = (blockIdx.x - 1024) * 256 + tid;
        int stride = 8 * 256;
        for (int i = ptid; i < 16 * 600; i += stride) {
            int d = i / 600, m = i - d * 600;
            g_krt[i] = (m <= 598) ? key_rel[m * 16 + d] : 0.f;
        }
        for (int i = ptid; i < 64 * 192; i += stride) {
            int c = i / 192, o = i - c * 192;
            g_Wt[i] = W[o * 64 + c];
        }
        for (int i = ptid; i < 64 * 64; i += stride) {
            int d = i >> 6, o = i & 63;
            g_Wat[i] = Wa[o * 64 + d];
        }
    }
}

// ---------------------------------------------------------------------------
// Kernel 1: 1x1 qkv conv over pre-normalized g_xbn (R15/R16 version).
// ---------------------------------------------------------------------------
__global__ void __launch_bounds__(256, 3) qkv_kernel(const float* __restrict__ Wb)
{
    int b = blockIdx.x;
    int T0 = blockIdx.y * 100;
    extern __shared__ float sm[];
    float* xs = sm;             // 64*100
    float* Wt = xs + 6400;      // 12288  [c][o]
    int tid = threadIdx.x;

    for (int i = tid; i < 3072; i += 256)
        ((float4*)Wt)[i] = ((const float4*)g_Wt)[i];
    const float* xb = g_xbn + (size_t)b * 64 * Tt + T0;
    for (int i = tid; i < 1600; i += 256) {
        int c = i / 25, t4 = i - c * 25;
        ((float4*)(xs + c * 100))[t4] = *(const float4*)(xb + c * Tt + t4 * 4);
    }
    __syncthreads();

    for (int task = tid; task < 624; task += 256) {
        int og = task % 48, tg = task / 48;
        int o0 = og * 4, t0 = tg * 8;
        bool full = (tg < 12);
        float acc[4][8];
        #pragma unroll
        for (int i = 0; i < 4; ++i)
            #pragma unroll
            for (int j = 0; j < 8; ++j) acc[i][j] = 0.f;

        if (full) {
            #pragma unroll 8
            for (int c = 0; c < 64; ++c) {
                float4 w4 = *(const float4*)(Wt + c * 192 + o0);
                float4 xa = *(const float4*)(xs + c * 100 + t0);
                float4 xc = *(const float4*)(xs + c * 100 + t0 + 4);
                float wa[4] = {w4.x, w4.y, w4.z, w4.w};
                float A[8] = {xa.x, xa.y, xa.z, xa.w, xc.x, xc.y, xc.z, xc.w};
                #pragma unroll
                for (int i = 0; i < 4; ++i)
                    #pragma unroll
                    for (int j = 0; j < 8; ++j)
                        acc[i][j] += wa[i] * A[j];
            }
        } else {
            #pragma unroll 8
            for (int c = 0; c < 64; ++c) {
                float4 w4 = *(const float4*)(Wt + c * 192 + o0);
                float4 xa = *(const float4*)(xs + c * 100 + t0);
                float wa[4] = {w4.x, w4.y, w4.z, w4.w};
                float A[4] = {xa.x, xa.y, xa.z, xa.w};
                #pragma unroll
                for (int i = 0; i < 4; ++i)
                    #pragma unroll
                    for (int j = 0; j < 4; ++j)
                        acc[i][j] += wa[i] * A[j];
            }
        }

        float* outp = g_qkv + ((size_t)b * QKVO + o0) * Tt + T0 + t0;
        #pragma unroll
        for (int i = 0; i < 4; ++i) {
            float bias = Wb[o0 + i];
            float scale = (o0 + i < 64) ? 0.25f : 1.0f;  // q * DKH^-0.5
            float4 r;
            r.x = (acc[i][0] + bias) * scale;
            r.y = (acc[i][1] + bias) * scale;
            r.z = (acc[i][2] + bias) * scale;
            r.w = (acc[i][3] + bias) * scale;
            *(float4*)(outp + i * Tt) = r;
            if (full) {
                float4 r2;
                r2.x = (acc[i][4] + bias) * scale;
                r2.y = (acc[i][5] + bias) * scale;
                r2.z = (acc[i][6] + bias) * scale;
                r2.w = (acc[i][7] + bias) * scale;
                *(float4*)(outp + i * Tt + 4) = r2;
            }
        }
    }
}

// ---------------------------------------------------------------------------
// Kernel 2: attention per (b,h). QK+softmax: R16 (base-2, register logits).
// AV v3: d-major vs, L float2 consumed directly by FFMA2 (no extract/pack),
// 4 sweeps of 4 head-dims, scalar select-merge butterfly.
// ---------------------------------------------------------------------------
#define KST 300   // ks row stride
#define RST 600   // krs row stride
#define VST 304   // vs row stride (16B-aligned rows)
#define LOG2E 1.4426950408889634f

__global__ void __launch_bounds__(ATH, 2) attn_kernel()
{
    int bh = blockIdx.x;
    int b = bh >> 2, h = bh & 3;
    int nn = b / Vv, vv = b - nn * Vv;
    extern __shared__ float sm[];
    float* ks  = sm;                  // 16*300  [d][s]
    float* krs = ks + 16 * KST;       // 16*600  [d][m]
    float* vs  = krs + 16 * RST;      // 16*304  [d][s]

    const float* base = g_qkv + (size_t)b * QKVO * Tt;
    const float* qg = base + (h * 16) * Tt;
    const float* kg = base + (64 + h * 16) * Tt;
    const float* vg = base + (128 + h * 16) * Tt;
    float* og_base = g_attn + ((size_t)nn * 64 + h * 16) * TJ + vv;

    int tid = threadIdx.x;
    for (int i = tid; i < 1200; i += ATH)
        ((float4*)ks)[i] = ((const float4*)kg)[i];
    for (int i = tid; i < 2400; i += ATH)
        ((float4*)krs)[i] = ((const float4*)g_krt)[i];
    for (int i = tid; i < 1200; i += ATH) {
        int d = i / 75, r = i - d * 75;
        ((float4*)(vs + d * VST))[r] = ((const float4*)(vg + d * 300))[r];
    }
    __syncthreads();

    int warp = tid >> 5, lane = tid & 31;
    int oi = (((lane >> 4) & 1) << 1) | ((lane >> 3) & 1);
    int odp = (((lane >> 2) & 1) << 1) | ((lane >> 1) & 1);

    for (int g = warp; g < 75; g += 10) {
        int t0 = g * 4;
        float2 L[3][4][2];
        bool v2 = (lane < 11);
        #pragma unroll
        for (int p = 0; p < 3; ++p) {
            float init = (p < 2 || v2) ? 0.f : -1e30f;
            #pragma unroll
            for (int i = 0; i < 4; ++i) {
                L[p][i][0] = make_float2(init, init);
                L[p][i][1] = make_float2(init, init);
            }
        }

        // ---- QK + rel (packed over s-pairs), base-2 ----
        #pragma unroll
        for (int d = 0; d < 16; ++d) {
            float4 q4 = __ldg((const float4*)(qg + d * 300 + t0));
            float2 qd[4] = { make_float2(q4.x * LOG2E, q4.x * LOG2E),
                             make_float2(q4.y * LOG2E, q4.y * LOG2E),
                             make_float2(q4.z * LOG2E, q4.z * LOG2E),
                             make_float2(q4.w * LOG2E, q4.w * LOG2E) };
            #pragma unroll
            for (int p = 0; p < 3; ++p) {
                if (p < 2 || v2) {
                    int s0 = p * 128 + lane * 4;
                    int m0 = s0 - t0 + 296;
                    float4 k4 = *(const float4*)(ks + d * KST + s0);
                    float4 ra = *(const float4*)(krs + d * RST + m0);
                    float4 rb = *(const float4*)(krs + d * RST + m0 + 4);
                    float2 k01 = make_float2(k4.x, k4.y), k23 = make_float2(k4.z, k4.w);
                    float2 r01 = make_float2(ra.x, ra.y), r23 = make_float2(ra.z, ra.w);
                    float2 r45 = make_float2(rb.x, rb.y);
                    float2 r12 = make_float2(ra.y, ra.z);
                    float2 r34 = make_float2(ra.w, rb.x);
                    float2 r56 = make_float2(rb.y, rb.z);
                    L[p][0][0] = ffma2(qd[0], k01, L[p][0][0]); L[p][0][1] = ffma2(qd[0], k23, L[p][0][1]);
                    L[p][1][0] = ffma2(qd[1], k01, L[p][1][0]); L[p][1][1] = ffma2(qd[1], k23, L[p][1][1]);
                    L[p][2][0] = ffma2(qd[2], k01, L[p][2][0]); L[p][2][1] = ffma2(qd[2], k23, L[p][2][1]);
                    L[p][3][0] = ffma2(qd[3], k01, L[p][3][0]); L[p][3][1] = ffma2(qd[3], k23, L[p][3][1]);
                    L[p][0][0] = ffma2(qd[0], r34, L[p][0][0]); L[p][0][1] = ffma2(qd[0], r56, L[p][0][1]);
                    L[p][1][0] = ffma2(qd[1], r23, L[p][1][0]); L[p][1][1] = ffma2(qd[1], r45, L[p][1][1]);
                    L[p][2][0] = ffma2(qd[2], r12, L[p][2][0]); L[p][2][1] = ffma2(qd[2], r34, L[p][2][1]);
                    L[p][3][0] = ffma2(qd[3], r01, L[p][3][0]); L[p][3][1] = ffma2(qd[3], r23, L[p][3][1]);
                }
            }
        }

        // ---- softmax per row (base 2) ----
        #pragma unroll
        for (int i = 0; i < 4; ++i) {
            float mx = -1e30f;
            #pragma unroll
            for (int p = 0; p < 3; ++p)
                #pragma unroll
                for (int jp = 0; jp < 2; ++jp)
                    mx = fmaxf(mx, fmaxf(L[p][i][jp].x, L[p][i][jp].y));
            #pragma unroll
            for (int o = 16; o > 0; o >>= 1)
                mx = fmaxf(mx, __shfl_xor_sync(0xffffffffu, mx, o));
            float s = 0.f;
            #pragma unroll
            for (int p = 0; p < 3; ++p)
                #pragma unroll
                for (int jp = 0; jp < 2; ++jp) {
                    float ex = exp2f(L[p][i][jp].x - mx);
                    float ey = exp2f(L[p][i][jp].y - mx);
                    L[p][i][jp] = make_float2(ex, ey);
                    s += ex + ey;
                }
            #pragma unroll
            for (int o = 16; o > 0; o >>= 1)
                s += __shfl_xor_sync(0xffffffffu, s, o);
            float inv = 1.f / s;
            float2 inv2 = make_float2(inv, inv);
            #pragma unroll
            for (int p = 0; p < 3; ++p)
                #pragma unroll
                for (int jp = 0; jp < 2; ++jp)
                    L[p][i][jp] = fmul2(L[p][i][jp], inv2);
        }

        // ---- AV v3: 4 sweeps of 4 head-dims; L consumed directly ----
        #pragma unroll
        for (int sweep = 0; sweep < 4; ++sweep) {
            float2 racc[16];   // [i*4 + c], accumulated over s-pairs
            #pragma unroll
            for (int k = 0; k < 16; ++k) racc[k] = make_float2(0.f, 0.f);

            #pragma unroll
            for (int p = 0; p < 3; ++p) {
                int sbase = p * 128 + lane * 4;
                if (sbase > 296) sbase = 296;    // invalid lanes: probs are 0
                #pragma unroll
                for (int c = 0; c < 4; ++c) {
                    int dd = sweep * 4 + c;
                    float4 v4 = *(const float4*)(vs + dd * VST + sbase);
                    float2 v01 = make_float2(v4.x, v4.y);
                    float2 v23 = make_float2(v4.z, v4.w);
                    #pragma unroll
                    for (int i = 0; i < 4; ++i) {
                        racc[i * 4 + c] = ffma2(L[p][i][0], v01, racc[i * 4 + c]);
                        racc[i * 4 + c] = ffma2(L[p][i][1], v23, racc[i * 4 + c]);
                    }
                }
            }

            // horizontal add over the s-pair
            float rs[16];
            #pragma unroll
            for (int k = 0; k < 16; ++k) rs[k] = racc[k].x + racc[k].y;

            // select-merge butterfly: 16 scalars -> 16 outputs over 32 lanes
            bool hi;
            hi = (lane & 16);
            #pragma unroll
            for (int k = 0; k < 8; ++k) {
                float keep = hi ? rs[k + 8] : rs[k];
                float send = hi ? rs[k] : rs[k + 8];
                rs[k] = keep + __shfl_xor_sync(0xffffffffu, send, 16);
            }
            hi = (lane & 8);
            #pragma unroll
            for (int k = 0; k < 4; ++k) {
                float keep = hi ? rs[k + 4] : rs[k];
                float send = hi ? rs[k] : rs[k + 4];
                rs[k] = keep + __shfl_xor_sync(0xffffffffu, send, 8);
            }
            hi = (lane & 4);
            #pragma unroll
            for (int k = 0; k < 2; ++k) {
                float keep = hi ? rs[k + 2] : rs[k];
                float send = hi ? rs[k] : rs[k + 2];
                rs[k] = keep + __shfl_xor_sync(0xffffffffu, send, 4);
            }
            hi = (lane & 2);
            {
                float keep = hi ? rs[1] : rs[0];
                float send = hi ? rs[0] : rs[1];
                rs[0] = keep + __shfl_xor_sync(0xffffffffu, send, 2);
            }
            rs[0] += __shfl_xor_sync(0xffffffffu, rs[0], 1);
            if (!(lane & 1)) {
                int d = sweep * 4 + odp;
                og_base[(size_t)d * TJ + (t0 + oi) * 25] = rs[0];
            }
        }
    }
}

// ---------------------------------------------------------------------------
// Kernel 3: proj — half-j-tiles, 4o x 4j register tile, 4 CTA/SM (R16 version).
// ---------------------------------------------------------------------------
__global__ void __launch_bounds__(256, 4) proj_kernel(
    const float* __restrict__ Ba,
    const float* __restrict__ bg, const float* __restrict__ bb,
    const float* __restrict__ bm, const float* __restrict__ bv,
    const float* __restrict__ x, float* __restrict__ out)
{
    int n = blockIdx.x;
    int jt = blockIdx.y;
    int half = blockIdx.z;
    int j0 = jt * 300 + half * 152;
    int JL = half ? 148 : 152;
    extern __shared__ float sm[];
    float* as = sm;            // 64*152  [d][jj]
    float* Wt = as + 64 * 152; // 64*64   [d][o]
    float* s2 = Wt + 4096;     // 64
    float* b2 = s2 + 64;       // 64
    int tid = threadIdx.x;

    int nf4 = JL >> 2;
    for (int i = tid; i < 64 * nf4; i += 256) {
        int d = i / nf4, r = i - d * nf4;
        ((float4*)(as + d * 152))[r] =
            ((const float4*)(g_attn + (size_t)(n * 64 + d) * TJ + j0))[r];
    }
    if (half) {
        for (int i = tid; i < 256; i += 256) {
            int d = i >> 2;
            as[d * 152 + 148 + (i & 3)] = 0.f;
        }
    }
    for (int i = tid; i < 1024; i += 256)
        ((float4*)Wt)[i] = ((const float4*)g_Wat)[i];
    if (tid < 64) {
        float s = bg[tid] * rsqrtf(bv[tid] + 1e-5f);
        s2[tid] = s;
        b2[tid] = bb[tid] - bm[tid] * s;
    }
    __syncthreads();

    const float* xb = x + (size_t)n * 64 * TJ + j0;
    float*       ob = out + (size_t)n * 64 * TJ + j0;

    for (int task = tid; task < 608; task += 256) {
        int og = task & 15, jg = task >> 4;
        int o0 = og * 4, jj0 = jg * 4;
        float acc[4][4] = {};
        #pragma unroll 8
        for (int d = 0; d < 64; ++d) {
            float4 w4 = *(const float4*)(Wt + d * 64 + o0);
            float4 a4 = *(const float4*)(as + d * 152 + jj0);
            float wa[4] = {w4.x, w4.y, w4.z, w4.w};
            float aa[4] = {a4.x, a4.y, a4.z, a4.w};
            #pragma unroll
            for (int i = 0; i < 4; ++i)
                #pragma unroll
                for (int j = 0; j < 4; ++j)
                    acc[i][j] += wa[i] * aa[j];
        }
        bool valid = (jj0 < JL);
        if (valid) {
            #pragma unroll
            for (int i = 0; i < 4; ++i) {
                int o = o0 + i;
                float bias = Ba[o];
                float ss = s2[o], bb2 = b2[o];
                const float* xo = xb + (size_t)o * TJ + jj0;
                float*       oo = ob + (size_t)o * TJ + jj0;
                float4 xv = *(const float4*)(xo);
                float4 r;
                r.x = fmaxf((acc[i][0] + bias + xv.x) * ss + bb2, 0.f);
                r.y = fmaxf((acc[i][1] + bias + xv.y) * ss + bb2, 0.f);
                r.z = fmaxf((acc[i][2] + bias + xv.z) * ss + bb2, 0.f);
                r.w = fmaxf((acc[i][3] + bias + xv.w) * ss + bb2, 0.f);
                *(float4*)(oo) = r;
            }
        }
    }
}

// ---------------------------------------------------------------------------
extern "C" void kernel_launch(void* const* d_in, const int* in_sizes, int n_in,
                              void* d_out, int out_size)
{
    const float* x       = (const float*)d_in[0];
    const float* dbn_g   = (const float*)d_in[1];
    const float* dbn_b   = (const float*)d_in[2];
    const float* dbn_m   = (const float*)d_in[3];
    const float* dbn_v   = (const float*)d_in[4];
    const float* qkv_w   = (const float*)d_in[5];
    const float* qkv_b   = (const float*)d_in[6];
    const float* key_rel = (const float*)d_in[7];
    const float* attn_w  = (const float*)d_in[8];
    const float* attn_b  = (const float*)d_in[9];
    const float* bn_g    = (const float*)d_in[10];
    const float* bn_b    = (const float*)d_in[11];
    const float* bn_m    = (const float*)d_in[12];
    const float* bn_v    = (const float*)d_in[13];
    float* out = (float*)d_out;

    const int SM1 = (6400 + 12288) * 4;                    // 74,752
    const int SM2 = (16 * KST + 16 * RST + 16 * VST) * 4;  // 77,056
    const int SM3 = (64 * 152 + 4096 + 128) * 4;           // 55,808

    cudaFuncSetAttribute(qkv_kernel,  cudaFuncAttributeMaxDynamicSharedMemorySize, SM1);
    cudaFuncSetAttribute(attn_kernel, cudaFuncAttributeMaxDynamicSharedMemorySize, SM2);
    cudaFuncSetAttribute(proj_kernel, cudaFuncAttributeMaxDynamicSharedMemorySize, SM3);

    setup_kernel<<<1032, 256>>>(x, dbn_g, dbn_b, dbn_m, dbn_v, key_rel, qkv_w, attn_w);
    qkv_kernel<<<dim3(Bb, 3), 256, SM1>>>(qkv_b);
    attn_kernel<<<Bb * NHh, ATH, SM2>>>();
    proj_kernel<<<dim3(Nn, 25, 2), 256, SM3>>>(attn_b, bn_g, bn_b, bn_m, bn_v, x, out);
}